// round 5
// baseline (speedup 1.0000x reference)
#include <cuda_runtime.h>
#include <math.h>

#define B_     32
#define N_     197
#define D_     768
#define H_     12
#define HD_    64
#define DEPTH_ 12
#define MLP_   3072
#define QKVD_  2304
#define NPATCH_ 196
#define NN_    (N_*N_)
#define TOK_   (B_*N_)          /* 6304 */
#define PTOK_  (B_*NPATCH_)     /* 6272 */
#define SCALE_ 0.125f

/* ---------------- scratch (no allocations allowed) ---------------- */
__device__ float g_xp [PTOK_*D_];
__device__ float g_pe [PTOK_*D_];
__device__ float g_t  [TOK_*D_];
__device__ float g_h  [TOK_*D_];
__device__ float g_qkv[TOK_*QKVD_];
__device__ float g_a  [B_*H_*NN_];
__device__ float g_a2 [B_*H_*NN_];
__device__ float g_o  [TOK_*D_];
__device__ float g_mlp[TOK_*MLP_];
__device__ float g_cls[B_*D_];

/* ---------------- patch gather: x[B,3,224,224] -> xp[B,196,768] ---------------- */
__global__ void k_patch_gather(const float* __restrict__ x, float* __restrict__ xp) {
    int idx = blockIdx.x * blockDim.x + threadIdx.x;
    if (idx >= PTOK_*D_) return;
    int k = idx % D_;
    int p = (idx / D_) % NPATCH_;
    int b = idx / (D_ * NPATCH_);
    int c  = k >> 8;
    int iy = (k >> 4) & 15;
    int ix = k & 15;
    int py = p / 14, px = p % 14;
    xp[idx] = x[(((size_t)b*3 + c)*224 + py*16 + iy)*224 + px*16 + ix];
}

/* ---------------- assemble t = [cls | pe] + pos ---------------- */
__global__ void k_assemble(const float* __restrict__ pe, const float* __restrict__ cls,
                           const float* __restrict__ pos, float* __restrict__ t) {
    int idx = blockIdx.x * blockDim.x + threadIdx.x;
    if (idx >= TOK_*D_) return;
    int d = idx % D_;
    int n = (idx / D_) % N_;
    int b = idx / (D_ * N_);
    float v = (n == 0) ? cls[d] : pe[((size_t)b*NPATCH_ + (n-1))*D_ + d];
    t[idx] = v + pos[(size_t)n*D_ + d];
}

/* ---------------- generic GEMM: C[M,N] = A[M,K] * W[N,K]^T + bias; epilogues ----------------
   EPI: 0 = +bias, 1 = +bias then exact GELU, 2 = +bias then +res */
template<int EPI>
__global__ void k_gemm(const float* __restrict__ A, const float* __restrict__ W,
                       const float* __restrict__ bias, const float* __restrict__ res,
                       float* __restrict__ C, int M, int N, int K) {
    __shared__ float As[16][64];
    __shared__ float Bs[16][64];
    int tid = threadIdx.x;
    int tx = tid & 15, ty = tid >> 4;
    int row0 = blockIdx.y * 64;
    int col0 = blockIdx.x * 64;
    float acc[4][4] = {};
    for (int k0 = 0; k0 < K; k0 += 16) {
        #pragma unroll
        for (int i = 0; i < 4; i++) {
            int idx = tid + i*256;
            int r = idx >> 4, kk = idx & 15;
            int gr = row0 + r;
            As[kk][r] = (gr < M) ? A[(size_t)gr*K + k0 + kk] : 0.f;
            int gc = col0 + r;
            Bs[kk][r] = (gc < N) ? W[(size_t)gc*K + k0 + kk] : 0.f;
        }
        __syncthreads();
        #pragma unroll
        for (int kk = 0; kk < 16; kk++) {
            float4 av = *reinterpret_cast<const float4*>(&As[kk][ty*4]);
            float4 bv = *reinterpret_cast<const float4*>(&Bs[kk][tx*4]);
            float a4[4] = {av.x, av.y, av.z, av.w};
            float b4[4] = {bv.x, bv.y, bv.z, bv.w};
            #pragma unroll
            for (int i = 0; i < 4; i++)
                #pragma unroll
                for (int j = 0; j < 4; j++)
                    acc[i][j] += a4[i] * b4[j];
        }
        __syncthreads();
    }
    #pragma unroll
    for (int i = 0; i < 4; i++) {
        int r = row0 + ty*4 + i;
        if (r >= M) continue;
        #pragma unroll
        for (int j = 0; j < 4; j++) {
            int c = col0 + tx*4 + j;
            if (c >= N) continue;
            float v = acc[i][j] + bias[c];
            if (EPI == 1) v = 0.5f * v * (1.f + erff(v * 0.70710678118f));
            if (EPI == 2) v += res[(size_t)r*N + c];
            C[(size_t)r*N + c] = v;
        }
    }
}

/* ---------------- layernorm, row length 768, 256 threads/row ---------------- */
__global__ void k_layernorm(const float* __restrict__ in, const float* __restrict__ g,
                            const float* __restrict__ b, float* __restrict__ out,
                            size_t in_stride, size_t out_stride) {
    int row = blockIdx.x;
    const float* p = in + (size_t)row * in_stride;
    int t = threadIdx.x;
    float x0 = p[t], x1 = p[t+256], x2 = p[t+512];
    float s  = x0 + x1 + x2;
    float ss = x0*x0 + x1*x1 + x2*x2;
    __shared__ float rs[8], rss[8];
    for (int o = 16; o; o >>= 1) {
        s  += __shfl_xor_sync(0xffffffffu, s,  o);
        ss += __shfl_xor_sync(0xffffffffu, ss, o);
    }
    if ((t & 31) == 0) { rs[t>>5] = s; rss[t>>5] = ss; }
    __syncthreads();
    if (t < 8) { s = rs[t]; ss = rss[t]; }
    else       { s = 0.f;  ss = 0.f; }
    if (t < 32) {
        for (int o = 4; o; o >>= 1) {
            s  += __shfl_xor_sync(0xffffffffu, s,  o);
            ss += __shfl_xor_sync(0xffffffffu, ss, o);
        }
        if (t == 0) { rs[0] = s; rss[0] = ss; }
    }
    __syncthreads();
    float mean = rs[0] * (1.f/768.f);
    float var  = rss[0] * (1.f/768.f) - mean*mean;
    float inv  = rsqrtf(var + 1e-6f);
    float* q = out + (size_t)row * out_stride;
    q[t]     = (x0 - mean) * inv * g[t]     + b[t];
    q[t+256] = (x1 - mean) * inv * g[t+256] + b[t+256];
    q[t+512] = (x2 - mean) * inv * g[t+512] + b[t+512];
}

/* ---------------- attention scores: a[b,h,n,m] = scale * q.k ---------------- */
__global__ void k_attn_scores(const float* __restrict__ qkv, float* __restrict__ a) {
    int bh = blockIdx.z;
    int b = bh / H_, h = bh % H_;
    int n0 = blockIdx.y * 32, m0 = blockIdx.x * 32;
    __shared__ float Qs[32][64];
    __shared__ float Ks[32][64];
    const float* qb = qkv + (size_t)b * N_ * QKVD_ + h * HD_;
    for (int i = threadIdx.x; i < 32*64; i += 256) {
        int r = i >> 6, c = i & 63;
        int n = n0 + r;
        Qs[r][c] = (n < N_) ? qb[(size_t)n*QKVD_ + c] : 0.f;
        int m = m0 + r;
        Ks[r][c] = (m < N_) ? qb[(size_t)m*QKVD_ + D_ + c] : 0.f;
    }
    __syncthreads();
    int ty = threadIdx.x >> 4, tx = threadIdx.x & 15;
    float acc[2][2] = {};
    #pragma unroll
    for (int k = 0; k < 64; k++) {
        float q0 = Qs[ty*2][k],   q1 = Qs[ty*2+1][k];
        float kk0 = Ks[tx*2][k],  kk1 = Ks[tx*2+1][k];
        acc[0][0] += q0*kk0; acc[0][1] += q0*kk1;
        acc[1][0] += q1*kk0; acc[1][1] += q1*kk1;
    }
    float* ab = a + (size_t)bh * NN_;
    #pragma unroll
    for (int i = 0; i < 2; i++)
        #pragma unroll
        for (int j = 0; j < 2; j++) {
            int n = n0 + ty*2 + i, m = m0 + tx*2 + j;
            if (n < N_ && m < N_) ab[(size_t)n*N_ + m] = acc[i][j] * SCALE_;
        }
}

/* ---------------- talking-heads mix: out[b,g,n,m] = sum_h w[g,h] in[b,h,n,m] ---------------- */
__global__ void k_th_mix(const float* __restrict__ in, const float* __restrict__ w,
                         float* __restrict__ out) {
    __shared__ float ws[H_*H_];
    if (threadIdx.x < H_*H_) ws[threadIdx.x] = w[threadIdx.x];
    __syncthreads();
    size_t idx = (size_t)blockIdx.x * blockDim.x + threadIdx.x;
    if (idx >= (size_t)B_ * NN_) return;
    size_t b = idx / NN_, nm = idx % NN_;
    const float* ip = in  + b * H_ * NN_ + nm;
    float* op       = out + b * H_ * NN_ + nm;
    float vals[H_];
    #pragma unroll
    for (int h = 0; h < H_; h++) vals[h] = ip[(size_t)h * NN_];
    #pragma unroll
    for (int g = 0; g < H_; g++) {
        float s = 0.f;
        #pragma unroll
        for (int h = 0; h < H_; h++) s += ws[g*H_ + h] * vals[h];
        op[(size_t)g * NN_] = s;
    }
}

/* ---------------- softmax over last dim (197), one warp per row ---------------- */
__global__ void k_softmax(float* __restrict__ a) {
    int row = blockIdx.x * 8 + (threadIdx.x >> 5);
    int lane = threadIdx.x & 31;
    if (row >= B_*H_*N_) return;
    float* p = a + (size_t)row * N_;
    float v[7];
    float mx = -1e30f;
    #pragma unroll
    for (int i = 0; i < 7; i++) {
        int c = lane + i*32;
        v[i] = (c < N_) ? p[c] : -1e30f;
        mx = fmaxf(mx, v[i]);
    }
    for (int o = 16; o; o >>= 1) mx = fmaxf(mx, __shfl_xor_sync(0xffffffffu, mx, o));
    float s = 0.f;
    #pragma unroll
    for (int i = 0; i < 7; i++) {
        int c = lane + i*32;
        v[i] = (c < N_) ? __expf(v[i] - mx) : 0.f;
        s += v[i];
    }
    for (int o = 16; o; o >>= 1) s += __shfl_xor_sync(0xffffffffu, s, o);
    float inv = 1.f / s;
    #pragma unroll
    for (int i = 0; i < 7; i++) {
        int c = lane + i*32;
        if (c < N_) p[c] = v[i] * inv;
    }
}

/* ---------------- AV: o[b,n,h*64+d] = sum_m a[b,h,n,m] v[b,m,h*64+d] ---------------- */
__global__ void k_attn_av(const float* __restrict__ a, const float* __restrict__ qkv,
                          float* __restrict__ o) {
    int bh = blockIdx.z;
    int b = bh / H_, h = bh % H_;
    int n0 = blockIdx.x * 32;
    const float* ab = a + (size_t)bh * NN_;
    const float* vb = qkv + (size_t)b * N_ * QKVD_ + 2*D_ + h * HD_;
    __shared__ float As[32][33];
    __shared__ float Vs[32][64];
    int ty = threadIdx.x >> 4, tx = threadIdx.x & 15;
    float acc[2][4] = {};
    for (int m0 = 0; m0 < N_; m0 += 32) {
        for (int i = threadIdx.x; i < 32*32; i += 256) {
            int r = i >> 5, c = i & 31;
            int n = n0 + r, m = m0 + c;
            As[r][c] = (n < N_ && m < N_) ? ab[(size_t)n*N_ + m] : 0.f;
        }
        for (int i = threadIdx.x; i < 32*64; i += 256) {
            int r = i >> 6, c = i & 63;
            int m = m0 + r;
            Vs[r][c] = (m < N_) ? vb[(size_t)m*QKVD_ + c] : 0.f;
        }
        __syncthreads();
        #pragma unroll
        for (int k = 0; k < 32; k++) {
            float a0 = As[ty*2][k], a1 = As[ty*2+1][k];
            float4 vv = *reinterpret_cast<const float4*>(&Vs[k][tx*4]);
            float v4[4] = {vv.x, vv.y, vv.z, vv.w};
            #pragma unroll
            for (int j = 0; j < 4; j++) { acc[0][j] += a0 * v4[j]; acc[1][j] += a1 * v4[j]; }
        }
        __syncthreads();
    }
    float* ob = o + (size_t)b * N_ * D_ + h * HD_;
    #pragma unroll
    for (int i = 0; i < 2; i++) {
        int n = n0 + ty*2 + i;
        if (n >= N_) continue;
        #pragma unroll
        for (int j = 0; j < 4; j++)
            ob[(size_t)n*D_ + tx*4 + j] = acc[i][j];
    }
}

/* ---------------- launch ---------------- */
static inline void* sym(const void* s) { void* p; cudaGetSymbolAddress(&p, s); return p; }

extern "C" void kernel_launch(void* const* d_in, const int* in_sizes, int n_in,
                              void* d_out, int out_size) {
    const float* x      = (const float*)d_in[0];
    const float* Wpe    = (const float*)d_in[1];
    const float* bpe    = (const float*)d_in[2];
    const float* cls    = (const float*)d_in[3];
    const float* pos    = (const float*)d_in[4];
    const float* ln1_g  = (const float*)d_in[5];
    const float* ln1_b  = (const float*)d_in[6];
    const float* qkv_w  = (const float*)d_in[7];
    const float* qkv_b  = (const float*)d_in[8];
    const float* pre_w  = (const float*)d_in[9];
    const float* post_w = (const float*)d_in[10];
    const float* proj_w = (const float*)d_in[11];
    const float* proj_b = (const float*)d_in[12];
    const float* ln2_g  = (const float*)d_in[13];
    const float* ln2_b  = (const float*)d_in[14];
    const float* fc1_w  = (const float*)d_in[15];
    const float* fc1_b  = (const float*)d_in[16];
    const float* fc2_w  = (const float*)d_in[17];
    const float* fc2_b  = (const float*)d_in[18];
    const float* lnf_g  = (const float*)d_in[19];
    const float* lnf_b  = (const float*)d_in[20];
    const float* head_w = (const float*)d_in[21];
    const float* head_b = (const float*)d_in[22];
    float* out = (float*)d_out;

    float* xp  = (float*)sym(g_xp);
    float* pe  = (float*)sym(g_pe);
    float* t   = (float*)sym(g_t);
    float* h   = (float*)sym(g_h);
    float* qkv = (float*)sym(g_qkv);
    float* a   = (float*)sym(g_a);
    float* a2  = (float*)sym(g_a2);
    float* o   = (float*)sym(g_o);
    float* mlp = (float*)sym(g_mlp);
    float* clsb= (float*)sym(g_cls);

    /* patch embed */
    k_patch_gather<<<(PTOK_*D_ + 255)/256, 256>>>(x, xp);
    {
        dim3 g((D_+63)/64, (PTOK_+63)/64);
        k_gemm<0><<<g, 256>>>(xp, Wpe, bpe, nullptr, pe, PTOK_, D_, D_);
    }
    k_assemble<<<(TOK_*D_ + 255)/256, 256>>>(pe, cls, pos, t);

    for (int L = 0; L < DEPTH_; L++) {
        const float* l1g = ln1_g + L*D_;
        const float* l1b = ln1_b + L*D_;
        const float* qw  = qkv_w + (size_t)L*QKVD_*D_;
        const float* qb  = qkv_b + L*QKVD_;
        const float* wpr = pre_w  + L*H_*H_;
        const float* wpo = post_w + L*H_*H_;
        const float* pw  = proj_w + (size_t)L*D_*D_;
        const float* pb  = proj_b + L*D_;
        const float* l2g = ln2_g + L*D_;
        const float* l2b = ln2_b + L*D_;
        const float* f1w = fc1_w + (size_t)L*MLP_*D_;
        const float* f1b = fc1_b + L*MLP_;
        const float* f2w = fc2_w + (size_t)L*D_*MLP_;
        const float* f2b = fc2_b + L*D_;

        k_layernorm<<<TOK_, 256>>>(t, l1g, l1b, h, D_, D_);
        {
            dim3 g((QKVD_+63)/64, (TOK_+63)/64);
            k_gemm<0><<<g, 256>>>(h, qw, qb, nullptr, qkv, TOK_, QKVD_, D_);
        }
        {
            dim3 g((N_+31)/32, (N_+31)/32, B_*H_);
            k_attn_scores<<<g, 256>>>(qkv, a);
        }
        k_th_mix<<<(unsigned)(((size_t)B_*NN_ + 255)/256), 256>>>(a, wpr, a2);
        k_softmax<<<(B_*H_*N_ + 7)/8, 256>>>(a2);
        k_th_mix<<<(unsigned)(((size_t)B_*NN_ + 255)/256), 256>>>(a2, wpo, a);
        {
            dim3 g((N_+31)/32, 1, B_*H_);
            k_attn_av<<<g, 256>>>(a, qkv, o);
        }
        {
            dim3 g((D_+63)/64, (TOK_+63)/64);
            k_gemm<2><<<g, 256>>>(o, pw, pb, t, t, TOK_, D_, D_);
        }
        k_layernorm<<<TOK_, 256>>>(t, l2g, l2b, h, D_, D_);
        {
            dim3 g((MLP_+63)/64, (TOK_+63)/64);
            k_gemm<1><<<g, 256>>>(h, f1w, f1b, nullptr, mlp, TOK_, MLP_, D_);
        }
        {
            dim3 g((D_+63)/64, (TOK_+63)/64);
            k_gemm<2><<<g, 256>>>(mlp, f2w, f2b, t, t, TOK_, D_, MLP_);
        }
    }

    /* final LN on cls rows only, then head */
    k_layernorm<<<B_, 256>>>(t, lnf_g, lnf_b, clsb, (size_t)N_*D_, D_);
    {
        dim3 g((1000+63)/64, (B_+63)/64);
        k_gemm<0><<<g, 256>>>(clsb, head_w, head_b, nullptr, out, B_, 1000, D_);
    }
}

// round 7
// speedup vs baseline: 1.6214x; 1.6214x over previous
#include <cuda_runtime.h>
#include <cuda_bf16.h>
#include <cstdint>
#include <math.h>

#define B_     32
#define N_     197
#define D_     768
#define H_     12
#define HD_    64
#define DEPTH_ 12
#define MLP_   3072
#define QKVD_  2304
#define NPATCH_ 196
#define NN_    (N_*N_)
#define TOK_   (B_*N_)          /* 6304 */
#define PTOK_  (B_*NPATCH_)     /* 6272 */
#define SCALE_ 0.125f

/* ---------------- scratch (no allocations allowed) ---------------- */
__device__ float g_xp [PTOK_*D_];
__device__ float g_pe [PTOK_*D_];
__device__ float g_t  [TOK_*D_];
__device__ float g_h  [TOK_*D_];
__device__ float g_qkv[TOK_*QKVD_];
__device__ float g_a  [B_*H_*NN_];
__device__ float g_a2 [B_*H_*NN_];
__device__ float g_o  [TOK_*D_];
__device__ float g_mlp[TOK_*MLP_];
__device__ float g_cls[B_*D_];

/* ================= warp-MMA helpers (HMMA, portable PTX) ================= */
__device__ __forceinline__ void mma16816(float* c,
                                         uint32_t a0, uint32_t a1, uint32_t a2, uint32_t a3,
                                         uint32_t b0, uint32_t b1) {
    asm volatile("mma.sync.aligned.m16n8k16.row.col.f32.bf16.bf16.f32 "
        "{%0,%1,%2,%3}, {%4,%5,%6,%7}, {%8,%9}, {%0,%1,%2,%3};"
        : "+f"(c[0]), "+f"(c[1]), "+f"(c[2]), "+f"(c[3])
        : "r"(a0), "r"(a1), "r"(a2), "r"(a3), "r"(b0), "r"(b1));
}
__device__ __forceinline__ uint32_t pack_bf2(float lo_elem, float hi_elem) {
    __nv_bfloat16 a = __float2bfloat16(lo_elem);
    __nv_bfloat16 b = __float2bfloat16(hi_elem);
    return (uint32_t)__bfloat16_as_ushort(a) | ((uint32_t)__bfloat16_as_ushort(b) << 16);
}
__device__ __forceinline__ float bf16_rt(float x) {
    return __bfloat162float(__float2bfloat16(x));
}

/* ================= split-bf16 HMMA GEMM =================
   C[M,N] = A[M,K] * W[N,K]^T + bias ; fp32-accurate via hi/lo 3-pass.
   CTA tile 128x128, K chunk 32, 256 threads (8 warps, 2x4 of 64x32 warp tiles).
   EPI: 0=+bias, 1=+bias,GELU, 2=+bias,+res  */
#define TCM 128
#define TCN 128
#define TKC 32
#define SSTR 40   /* smem row stride in bf16 elements (conflict-free: 20 words) */

template<int EPI>
__global__ void __launch_bounds__(256, 1)
k_gemm_mma(const float* __restrict__ A, const float* __restrict__ W,
           const float* __restrict__ bias, const float* __restrict__ res,
           float* __restrict__ C, int M, int N, int K) {
    __shared__ __align__(16) uint16_t sAhi[128*SSTR];
    __shared__ __align__(16) uint16_t sAlo[128*SSTR];
    __shared__ __align__(16) uint16_t sBhi[128*SSTR];
    __shared__ __align__(16) uint16_t sBlo[128*SSTR];

    const int tid = threadIdx.x;
    const int wid = tid >> 5, lane = tid & 31;
    const int g = lane >> 2, t = lane & 3;
    const int wr = wid >> 2, wc = wid & 3;          /* warp grid 2x4 */
    const int row0 = blockIdx.y * TCM, col0 = blockIdx.x * TCN;

    float acc[4][4][4];
    #pragma unroll
    for (int i = 0; i < 4; i++)
        #pragma unroll
        for (int j = 0; j < 4; j++)
            #pragma unroll
            for (int e = 0; e < 4; e++) acc[i][j][e] = 0.f;

    const int nch = K / TKC;
    for (int ch = 0; ch < nch; ch++) {
        const int k0 = ch * TKC;
        /* ---- stage A tile (128 x 32 fp32 -> hi/lo bf16) ---- */
        #pragma unroll
        for (int it = 0; it < 4; it++) {
            int i = tid + it * 256;
            int r = i >> 3, q = i & 7;
            int gr = row0 + r;
            float4 v = make_float4(0.f, 0.f, 0.f, 0.f);
            if (gr < M) v = *reinterpret_cast<const float4*>(A + (size_t)gr*K + k0 + q*4);
            float hx = bf16_rt(v.x), hy = bf16_rt(v.y), hz = bf16_rt(v.z), hw = bf16_rt(v.w);
            *reinterpret_cast<uint2*>(&sAhi[r*SSTR + q*4]) =
                make_uint2(pack_bf2(v.x, v.y), pack_bf2(v.z, v.w));
            *reinterpret_cast<uint2*>(&sAlo[r*SSTR + q*4]) =
                make_uint2(pack_bf2(v.x - hx, v.y - hy), pack_bf2(v.z - hz, v.w - hw));
        }
        /* ---- stage B tile (128 n-rows x 32 fp32) ---- */
        #pragma unroll
        for (int it = 0; it < 4; it++) {
            int i = tid + it * 256;
            int r = i >> 3, q = i & 7;
            int gc = col0 + r;
            float4 v = make_float4(0.f, 0.f, 0.f, 0.f);
            if (gc < N) v = *reinterpret_cast<const float4*>(W + (size_t)gc*K + k0 + q*4);
            float hx = bf16_rt(v.x), hy = bf16_rt(v.y), hz = bf16_rt(v.z), hw = bf16_rt(v.w);
            *reinterpret_cast<uint2*>(&sBhi[r*SSTR + q*4]) =
                make_uint2(pack_bf2(v.x, v.y), pack_bf2(v.z, v.w));
            *reinterpret_cast<uint2*>(&sBlo[r*SSTR + q*4]) =
                make_uint2(pack_bf2(v.x - hx, v.y - hy), pack_bf2(v.z - hz, v.w - hw));
        }
        __syncthreads();

        #pragma unroll
        for (int ks = 0; ks < 2; ks++) {
            const int kb = ks * 16;
            uint32_t fAh[4][4], fAl[4][4], fBh[4][2], fBl[4][2];
            #pragma unroll
            for (int mt = 0; mt < 4; mt++) {
                int r0 = wr*64 + mt*16 + g;
                fAh[mt][0] = *reinterpret_cast<const uint32_t*>(&sAhi[(r0  )*SSTR + kb + 2*t]);
                fAh[mt][1] = *reinterpret_cast<const uint32_t*>(&sAhi[(r0+8)*SSTR + kb + 2*t]);
                fAh[mt][2] = *reinterpret_cast<const uint32_t*>(&sAhi[(r0  )*SSTR + kb + 8 + 2*t]);
                fAh[mt][3] = *reinterpret_cast<const uint32_t*>(&sAhi[(r0+8)*SSTR + kb + 8 + 2*t]);
                fAl[mt][0] = *reinterpret_cast<const uint32_t*>(&sAlo[(r0  )*SSTR + kb + 2*t]);
                fAl[mt][1] = *reinterpret_cast<const uint32_t*>(&sAlo[(r0+8)*SSTR + kb + 2*t]);
                fAl[mt][2] = *reinterpret_cast<const uint32_t*>(&sAlo[(r0  )*SSTR + kb + 8 + 2*t]);
                fAl[mt][3] = *reinterpret_cast<const uint32_t*>(&sAlo[(r0+8)*SSTR + kb + 8 + 2*t]);
            }
            #pragma unroll
            for (int nt = 0; nt < 4; nt++) {
                int n0 = wc*32 + nt*8 + g;
                fBh[nt][0] = *reinterpret_cast<const uint32_t*>(&sBhi[n0*SSTR + kb + 2*t]);
                fBh[nt][1] = *reinterpret_cast<const uint32_t*>(&sBhi[n0*SSTR + kb + 8 + 2*t]);
                fBl[nt][0] = *reinterpret_cast<const uint32_t*>(&sBlo[n0*SSTR + kb + 2*t]);
                fBl[nt][1] = *reinterpret_cast<const uint32_t*>(&sBlo[n0*SSTR + kb + 8 + 2*t]);
            }
            #pragma unroll
            for (int mt = 0; mt < 4; mt++)
                #pragma unroll
                for (int nt = 0; nt < 4; nt++) {
                    mma16816(acc[mt][nt], fAh[mt][0], fAh[mt][1], fAh[mt][2], fAh[mt][3],
                             fBh[nt][0], fBh[nt][1]);
                    mma16816(acc[mt][nt], fAh[mt][0], fAh[mt][1], fAh[mt][2], fAh[mt][3],
                             fBl[nt][0], fBl[nt][1]);
                    mma16816(acc[mt][nt], fAl[mt][0], fAl[mt][1], fAl[mt][2], fAl[mt][3],
                             fBh[nt][0], fBh[nt][1]);
                }
        }
        __syncthreads();
    }

    /* ---- epilogue ---- */
    #pragma unroll
    for (int mt = 0; mt < 4; mt++) {
        int r0 = row0 + wr*64 + mt*16 + g;
        #pragma unroll
        for (int nt = 0; nt < 4; nt++) {
            int cb = col0 + wc*32 + nt*8 + 2*t;
            #pragma unroll
            for (int e = 0; e < 4; e++) {
                int r = r0 + (e >> 1) * 8;
                int c = cb + (e & 1);
                if (r < M && c < N) {
                    float v = acc[mt][nt][e] + bias[c];
                    if (EPI == 1) v = 0.5f * v * (1.f + erff(v * 0.70710678118f));
                    if (EPI == 2) v += res[(size_t)r * N + c];
                    C[(size_t)r * N + c] = v;
                }
            }
        }
    }
}

/* ---------------- patch gather: x[B,3,224,224] -> xp[B,196,768] ---------------- */
__global__ void k_patch_gather(const float* __restrict__ x, float* __restrict__ xp) {
    int idx = blockIdx.x * blockDim.x + threadIdx.x;
    if (idx >= PTOK_*D_) return;
    int k = idx % D_;
    int p = (idx / D_) % NPATCH_;
    int b = idx / (D_ * NPATCH_);
    int c  = k >> 8;
    int iy = (k >> 4) & 15;
    int ix = k & 15;
    int py = p / 14, px = p % 14;
    xp[idx] = x[(((size_t)b*3 + c)*224 + py*16 + iy)*224 + px*16 + ix];
}

/* ---------------- assemble t = [cls | pe] + pos ---------------- */
__global__ void k_assemble(const float* __restrict__ pe, const float* __restrict__ cls,
                           const float* __restrict__ pos, float* __restrict__ t) {
    int idx = blockIdx.x * blockDim.x + threadIdx.x;
    if (idx >= TOK_*D_) return;
    int d = idx % D_;
    int n = (idx / D_) % N_;
    int b = idx / (D_ * N_);
    float v = (n == 0) ? cls[d] : pe[((size_t)b*NPATCH_ + (n-1))*D_ + d];
    t[idx] = v + pos[(size_t)n*D_ + d];
}

/* ---------------- layernorm, row length 768, 256 threads/row ---------------- */
__global__ void k_layernorm(const float* __restrict__ in, const float* __restrict__ g,
                            const float* __restrict__ b, float* __restrict__ out,
                            size_t in_stride, size_t out_stride) {
    int row = blockIdx.x;
    const float* p = in + (size_t)row * in_stride;
    int t = threadIdx.x;
    float x0 = p[t], x1 = p[t+256], x2 = p[t+512];
    float s  = x0 + x1 + x2;
    float ss = x0*x0 + x1*x1 + x2*x2;
    __shared__ float rs[8], rss[8];
    for (int o = 16; o; o >>= 1) {
        s  += __shfl_xor_sync(0xffffffffu, s,  o);
        ss += __shfl_xor_sync(0xffffffffu, ss, o);
    }
    if ((t & 31) == 0) { rs[t>>5] = s; rss[t>>5] = ss; }
    __syncthreads();
    if (t < 8) { s = rs[t]; ss = rss[t]; }
    else       { s = 0.f;  ss = 0.f; }
    if (t < 32) {
        for (int o = 4; o; o >>= 1) {
            s  += __shfl_xor_sync(0xffffffffu, s,  o);
            ss += __shfl_xor_sync(0xffffffffu, ss, o);
        }
        if (t == 0) { rs[0] = s; rss[0] = ss; }
    }
    __syncthreads();
    float mean = rs[0] * (1.f/768.f);
    float var  = rss[0] * (1.f/768.f) - mean*mean;
    float inv  = rsqrtf(var + 1e-6f);
    float* q = out + (size_t)row * out_stride;
    q[t]     = (x0 - mean) * inv * g[t]     + b[t];
    q[t+256] = (x1 - mean) * inv * g[t+256] + b[t+256];
    q[t+512] = (x2 - mean) * inv * g[t+512] + b[t+512];
}

/* ---------------- attention scores: a[b,h,n,m] = scale * q.k ---------------- */
__global__ void k_attn_scores(const float* __restrict__ qkv, float* __restrict__ a) {
    int bh = blockIdx.z;
    int b = bh / H_, h = bh % H_;
    int n0 = blockIdx.y * 32, m0 = blockIdx.x * 32;
    __shared__ float Qs[32][64];
    __shared__ float Ks[32][64];
    const float* qb = qkv + (size_t)b * N_ * QKVD_ + h * HD_;
    for (int i = threadIdx.x; i < 32*64; i += 256) {
        int r = i >> 6, c = i & 63;
        int n = n0 + r;
        Qs[r][c] = (n < N_) ? qb[(size_t)n*QKVD_ + c] : 0.f;
        int m = m0 + r;
        Ks[r][c] = (m < N_) ? qb[(size_t)m*QKVD_ + D_ + c] : 0.f;
    }
    __syncthreads();
    int ty = threadIdx.x >> 4, tx = threadIdx.x & 15;
    float acc[2][2] = {};
    #pragma unroll
    for (int k = 0; k < 64; k++) {
        float q0 = Qs[ty*2][k],   q1 = Qs[ty*2+1][k];
        float kk0 = Ks[tx*2][k],  kk1 = Ks[tx*2+1][k];
        acc[0][0] += q0*kk0; acc[0][1] += q0*kk1;
        acc[1][0] += q1*kk0; acc[1][1] += q1*kk1;
    }
    float* ab = a + (size_t)bh * NN_;
    #pragma unroll
    for (int i = 0; i < 2; i++)
        #pragma unroll
        for (int j = 0; j < 2; j++) {
            int n = n0 + ty*2 + i, m = m0 + tx*2 + j;
            if (n < N_ && m < N_) ab[(size_t)n*N_ + m] = acc[i][j] * SCALE_;
        }
}

/* ---------------- talking-heads mix ---------------- */
__global__ void k_th_mix(const float* __restrict__ in, const float* __restrict__ w,
                         float* __restrict__ out) {
    __shared__ float ws[H_*H_];
    if (threadIdx.x < H_*H_) ws[threadIdx.x] = w[threadIdx.x];
    __syncthreads();
    size_t idx = (size_t)blockIdx.x * blockDim.x + threadIdx.x;
    if (idx >= (size_t)B_ * NN_) return;
    size_t b = idx / NN_, nm = idx % NN_;
    const float* ip = in  + b * H_ * NN_ + nm;
    float* op       = out + b * H_ * NN_ + nm;
    float vals[H_];
    #pragma unroll
    for (int h = 0; h < H_; h++) vals[h] = ip[(size_t)h * NN_];
    #pragma unroll
    for (int g = 0; g < H_; g++) {
        float s = 0.f;
        #pragma unroll
        for (int h = 0; h < H_; h++) s += ws[g*H_ + h] * vals[h];
        op[(size_t)g * NN_] = s;
    }
}

/* ---------------- softmax over last dim (197), one warp per row ---------------- */
__global__ void k_softmax(float* __restrict__ a) {
    int row = blockIdx.x * 8 + (threadIdx.x >> 5);
    int lane = threadIdx.x & 31;
    if (row >= B_*H_*N_) return;
    float* p = a + (size_t)row * N_;
    float v[7];
    float mx = -1e30f;
    #pragma unroll
    for (int i = 0; i < 7; i++) {
        int c = lane + i*32;
        v[i] = (c < N_) ? p[c] : -1e30f;
        mx = fmaxf(mx, v[i]);
    }
    for (int o = 16; o; o >>= 1) mx = fmaxf(mx, __shfl_xor_sync(0xffffffffu, mx, o));
    float s = 0.f;
    #pragma unroll
    for (int i = 0; i < 7; i++) {
        int c = lane + i*32;
        v[i] = (c < N_) ? __expf(v[i] - mx) : 0.f;
        s += v[i];
    }
    for (int o = 16; o; o >>= 1) s += __shfl_xor_sync(0xffffffffu, s, o);
    float inv = 1.f / s;
    #pragma unroll
    for (int i = 0; i < 7; i++) {
        int c = lane + i*32;
        if (c < N_) p[c] = v[i] * inv;
    }
}

/* ---------------- AV: o[b,n,h*64+d] = sum_m a[b,h,n,m] v[b,m,h*64+d] ---------------- */
__global__ void k_attn_av(const float* __restrict__ a, const float* __restrict__ qkv,
                          float* __restrict__ o) {
    int bh = blockIdx.z;
    int b = bh / H_, h = bh % H_;
    int n0 = blockIdx.x * 32;
    const float* ab = a + (size_t)bh * NN_;
    const float* vb = qkv + (size_t)b * N_ * QKVD_ + 2*D_ + h * HD_;
    __shared__ float As[32][33];
    __shared__ float Vs[32][64];
    int ty = threadIdx.x >> 4, tx = threadIdx.x & 15;
    float acc[2][4] = {};
    for (int m0 = 0; m0 < N_; m0 += 32) {
        for (int i = threadIdx.x; i < 32*32; i += 256) {
            int r = i >> 5, c = i & 31;
            int n = n0 + r, m = m0 + c;
            As[r][c] = (n < N_ && m < N_) ? ab[(size_t)n*N_ + m] : 0.f;
        }
        for (int i = threadIdx.x; i < 32*64; i += 256) {
            int r = i >> 6, c = i & 63;
            int m = m0 + r;
            Vs[r][c] = (m < N_) ? vb[(size_t)m*QKVD_ + c] : 0.f;
        }
        __syncthreads();
        #pragma unroll
        for (int k = 0; k < 32; k++) {
            float a0 = As[ty*2][k], a1 = As[ty*2+1][k];
            float4 vv = *reinterpret_cast<const float4*>(&Vs[k][tx*4]);
            float v4[4] = {vv.x, vv.y, vv.z, vv.w};
            #pragma unroll
            for (int j = 0; j < 4; j++) { acc[0][j] += a0 * v4[j]; acc[1][j] += a1 * v4[j]; }
        }
        __syncthreads();
    }
    float* ob = o + (size_t)b * N_ * D_ + h * HD_;
    #pragma unroll
    for (int i = 0; i < 2; i++) {
        int n = n0 + ty*2 + i;
        if (n >= N_) continue;
        #pragma unroll
        for (int j = 0; j < 4; j++)
            ob[(size_t)n*D_ + tx*4 + j] = acc[i][j];
    }
}

/* ---------------- launch ---------------- */
static inline void* sym(const void* s) { void* p; cudaGetSymbolAddress(&p, s); return p; }

extern "C" void kernel_launch(void* const* d_in, const int* in_sizes, int n_in,
                              void* d_out, int out_size) {
    const float* x      = (const float*)d_in[0];
    const float* Wpe    = (const float*)d_in[1];
    const float* bpe    = (const float*)d_in[2];
    const float* cls    = (const float*)d_in[3];
    const float* pos    = (const float*)d_in[4];
    const float* ln1_g  = (const float*)d_in[5];
    const float* ln1_b  = (const float*)d_in[6];
    const float* qkv_w  = (const float*)d_in[7];
    const float* qkv_b  = (const float*)d_in[8];
    const float* pre_w  = (const float*)d_in[9];
    const float* post_w = (const float*)d_in[10];
    const float* proj_w = (const float*)d_in[11];
    const float* proj_b = (const float*)d_in[12];
    const float* ln2_g  = (const float*)d_in[13];
    const float* ln2_b  = (const float*)d_in[14];
    const float* fc1_w  = (const float*)d_in[15];
    const float* fc1_b  = (const float*)d_in[16];
    const float* fc2_w  = (const float*)d_in[17];
    const float* fc2_b  = (const float*)d_in[18];
    const float* lnf_g  = (const float*)d_in[19];
    const float* lnf_b  = (const float*)d_in[20];
    const float* head_w = (const float*)d_in[21];
    const float* head_b = (const float*)d_in[22];
    float* out = (float*)d_out;

    float* xp  = (float*)sym(g_xp);
    float* pe  = (float*)sym(g_pe);
    float* t   = (float*)sym(g_t);
    float* h   = (float*)sym(g_h);
    float* qkv = (float*)sym(g_qkv);
    float* a   = (float*)sym(g_a);
    float* a2  = (float*)sym(g_a2);
    float* o   = (float*)sym(g_o);
    float* mlp = (float*)sym(g_mlp);
    float* clsb= (float*)sym(g_cls);

    /* patch embed */
    k_patch_gather<<<(PTOK_*D_ + 255)/256, 256>>>(x, xp);
    {
        dim3 g((D_+TCN-1)/TCN, (PTOK_+TCM-1)/TCM);
        k_gemm_mma<0><<<g, 256>>>(xp, Wpe, bpe, nullptr, pe, PTOK_, D_, D_);
    }
    k_assemble<<<(TOK_*D_ + 255)/256, 256>>>(pe, cls, pos, t);

    for (int L = 0; L < DEPTH_; L++) {
        const float* l1g = ln1_g + L*D_;
        const float* l1b = ln1_b + L*D_;
        const float* qw  = qkv_w + (size_t)L*QKVD_*D_;
        const float* qb  = qkv_b + L*QKVD_;
        const float* wpr = pre_w  + L*H_*H_;
        const float* wpo = post_w + L*H_*H_;
        const float* pw  = proj_w + (size_t)L*D_*D_;
        const float* pb  = proj_b + L*D_;
        const float* l2g = ln2_g + L*D_;
        const float* l2b = ln2_b + L*D_;
        const float* f1w = fc1_w + (size_t)L*MLP_*D_;
        const float* f1b = fc1_b + L*MLP_;
        const float* f2w = fc2_w + (size_t)L*D_*MLP_;
        const float* f2b = fc2_b + L*D_;

        k_layernorm<<<TOK_, 256>>>(t, l1g, l1b, h, D_, D_);
        {
            dim3 g((QKVD_+TCN-1)/TCN, (TOK_+TCM-1)/TCM);
            k_gemm_mma<0><<<g, 256>>>(h, qw, qb, nullptr, qkv, TOK_, QKVD_, D_);
        }
        {
            dim3 g((N_+31)/32, (N_+31)/32, B_*H_);
            k_attn_scores<<<g, 256>>>(qkv, a);
        }
        k_th_mix<<<(unsigned)(((size_t)B_*NN_ + 255)/256), 256>>>(a, wpr, a2);
        k_softmax<<<(B_*H_*N_ + 7)/8, 256>>>(a2);
        k_th_mix<<<(unsigned)(((size_t)B_*NN_ + 255)/256), 256>>>(a2, wpo, a);
        {
            dim3 g((N_+31)/32, 1, B_*H_);
            k_attn_av<<<g, 256>>>(a, qkv, o);
        }
        {
            dim3 g((D_+TCN-1)/TCN, (TOK_+TCM-1)/TCM);
            k_gemm_mma<2><<<g, 256>>>(o, pw, pb, t, t, TOK_, D_, D_);
        }
        k_layernorm<<<TOK_, 256>>>(t, l2g, l2b, h, D_, D_);
        {
            dim3 g((MLP_+TCN-1)/TCN, (TOK_+TCM-1)/TCM);
            k_gemm_mma<1><<<g, 256>>>(h, f1w, f1b, nullptr, mlp, TOK_, MLP_, D_);
        }
        {
            dim3 g((D_+TCN-1)/TCN, (TOK_+TCM-1)/TCM);
            k_gemm_mma<2><<<g, 256>>>(mlp, f2w, f2b, t, t, TOK_, D_, MLP_);
        }
    }

    /* final LN on cls rows only, then head */
    k_layernorm<<<B_, 256>>>(t, lnf_g, lnf_b, clsb, (size_t)N_*D_, D_);
    {
        dim3 g((1000+TCN-1)/TCN, (B_+TCM-1)/TCM);
        k_gemm_mma<0><<<g, 256>>>(clsb, head_w, head_b, nullptr, out, B_, 1000, D_);
    }
}

// round 9
// speedup vs baseline: 2.9989x; 1.8496x over previous
#include <cuda_runtime.h>
#include <cuda_bf16.h>
#include <cstdint>
#include <math.h>

#define B_     32
#define N_     197
#define D_     768
#define H_     12
#define HD_    64
#define DEPTH_ 12
#define MLP_   3072
#define QKVD_  2304
#define NPATCH_ 196
#define NN_    (N_*N_)
#define TOK_   (B_*N_)          /* 6304 */
#define PTOK_  (B_*NPATCH_)     /* 6272 */
#define SCALE_ 0.125f

/* ---------------- scratch (no allocations allowed) ---------------- */
__device__ float g_pe [PTOK_*D_];
__device__ float g_t  [TOK_*D_];
__device__ float g_qkv[TOK_*QKVD_];
__device__ float g_a  [B_*H_*NN_];
__device__ float g_cls[B_*D_];
/* bf16 hi/lo operand buffers */
__device__ __nv_bfloat16 g_whi[MLP_*D_], g_wlo[MLP_*D_];       /* weight split (max 3072x768) */
__device__ __nv_bfloat16 g_xhi[TOK_*D_], g_xlo[TOK_*D_];       /* bufA: xp, h, cls */
__device__ __nv_bfloat16 g_mhi[TOK_*MLP_], g_mlo[TOK_*MLP_];   /* bufM: o, mlp */

/* ================= helpers ================= */
__device__ __forceinline__ uint32_t smem_u32(const void* p) {
    uint32_t a;
    asm("{ .reg .u64 t; cvta.to.shared.u64 t, %1; cvt.u32.u64 %0, t; }" : "=r"(a) : "l"(p));
    return a;
}
__device__ __forceinline__ void mma16816(float* c,
                                         uint32_t a0, uint32_t a1, uint32_t a2, uint32_t a3,
                                         uint32_t b0, uint32_t b1) {
    asm volatile("mma.sync.aligned.m16n8k16.row.col.f32.bf16.bf16.f32 "
        "{%0,%1,%2,%3}, {%4,%5,%6,%7}, {%8,%9}, {%0,%1,%2,%3};"
        : "+f"(c[0]), "+f"(c[1]), "+f"(c[2]), "+f"(c[3])
        : "r"(a0), "r"(a1), "r"(a2), "r"(a3), "r"(b0), "r"(b1));
}
__device__ __forceinline__ void ldm4(uint32_t addr, uint32_t& r0, uint32_t& r1,
                                     uint32_t& r2, uint32_t& r3) {
    asm volatile("ldmatrix.sync.aligned.m8n8.x4.shared.b16 {%0,%1,%2,%3}, [%4];"
        : "=r"(r0), "=r"(r1), "=r"(r2), "=r"(r3) : "r"(addr));
}
__device__ __forceinline__ void cpa16(uint32_t dst, const void* src, int sz) {
    asm volatile("cp.async.cg.shared.global [%0], [%1], 16, %2;" :: "r"(dst), "l"(src), "r"(sz));
}
__device__ __forceinline__ void cpa_commit() {
    asm volatile("cp.async.commit_group;" ::: "memory");
}
__device__ __forceinline__ void cpa_wait1() {
    asm volatile("cp.async.wait_group 1;" ::: "memory");
}
__device__ __forceinline__ void cpa_wait0() {
    asm volatile("cp.async.wait_group 0;" ::: "memory");
}
__device__ __forceinline__ uint32_t pack_bf2(float a_, float b_) {
    __nv_bfloat16 a = __float2bfloat16(a_);
    __nv_bfloat16 b = __float2bfloat16(b_);
    return (uint32_t)__bfloat16_as_ushort(a) | ((uint32_t)__bfloat16_as_ushort(b) << 16);
}
__device__ __forceinline__ float bf16_rt(float x) {
    return __bfloat162float(__float2bfloat16(x));
}
__device__ __forceinline__ void split_store(__nv_bfloat16* hi, __nv_bfloat16* lo,
                                            size_t idx, float v) {
    __nv_bfloat16 h = __float2bfloat16(v);
    hi[idx] = h;
    lo[idx] = __float2bfloat16(v - __bfloat162float(h));
}

/* ================= split kernel: fp32 -> bf16 hi/lo ================= */
__global__ void k_split(const float* __restrict__ s, __nv_bfloat16* __restrict__ hi,
                        __nv_bfloat16* __restrict__ lo, int n4) {
    int i = blockIdx.x * blockDim.x + threadIdx.x;
    if (i >= n4) return;
    float4 v = reinterpret_cast<const float4*>(s)[i];
    float hx = bf16_rt(v.x), hy = bf16_rt(v.y), hz = bf16_rt(v.z), hw = bf16_rt(v.w);
    reinterpret_cast<uint2*>(hi)[i] = make_uint2(pack_bf2(v.x, v.y), pack_bf2(v.z, v.w));
    reinterpret_cast<uint2*>(lo)[i] = make_uint2(pack_bf2(v.x - hx, v.y - hy),
                                                 pack_bf2(v.z - hz, v.w - hw));
}

/* ================= split-bf16 HMMA GEMM, cp.async double-buffered =================
   C[M,N] = A[M,K] * W[N,K]^T + bias, A/W given as bf16 hi/lo pairs.
   CTA 128x128, K chunk 32, 256 threads (8 warps 2x4, warp tile 64x32).
   EPI: 0 = fp32 C = acc+bias
        1 = GELU(acc+bias) -> bf16 hi/lo (Chi/Clo)
        2 = fp32 C = acc+bias+res                                              */
#define SSTR 40
#define PIECE (128*SSTR)                 /* elements per piece */
#define GSMEM (2*4*PIECE*2)              /* bytes: 2 stages x 4 pieces */

template<int EPI>
__global__ void __launch_bounds__(256, 1)
k_gemm_bf(const __nv_bfloat16* __restrict__ Ahi, const __nv_bfloat16* __restrict__ Alo,
          const __nv_bfloat16* __restrict__ Bhi, const __nv_bfloat16* __restrict__ Blo,
          const float* __restrict__ bias, const float* __restrict__ res,
          float* __restrict__ C, __nv_bfloat16* __restrict__ Chi,
          __nv_bfloat16* __restrict__ Clo, int M, int N, int K) {
    extern __shared__ __align__(16) uint16_t sm[];
    const int tid = threadIdx.x;
    const int wid = tid >> 5, lane = tid & 31;
    const int g = lane >> 2, t = lane & 3;
    const int wr = wid >> 2, wc = wid & 3;
    const int row0 = blockIdx.y * 128, col0 = blockIdx.x * 128;
    const uint32_t smb = smem_u32(sm);

    /* ldmatrix per-thread offsets */
    const int l8 = lane & 7, sel = lane >> 3;
    const int aOff = (((sel & 1) << 3) + l8) * SSTR + ((sel & 2) << 2);  /* row*S + col */
    const int bOff = (((sel >> 1) << 3) + l8) * SSTR + ((sel & 1) << 3);

    float acc[4][4][4];
    #pragma unroll
    for (int i = 0; i < 4; i++)
        #pragma unroll
        for (int j = 0; j < 4; j++)
            #pragma unroll
            for (int e = 0; e < 4; e++) acc[i][j][e] = 0.f;

    const int nch = K >> 5;
    /* staging lambda expressed inline: stage chunk `ck` into buffer `stg` */
    auto stage = [&](int stg, int ck) {
        const int k0 = ck << 5;
        const uint32_t base = smb + stg * 4 * PIECE * 2;
        #pragma unroll
        for (int half = 0; half < 2; half++) {
            int s = tid + half * 256;
            int r = s >> 2, q = s & 3;
            uint32_t doff = (uint32_t)(r * SSTR + q * 8) * 2;
            int colb = k0 + q * 8;
            /* A pieces */
            int gr = row0 + r;
            int szA = (gr < M) ? 16 : 0;
            int grc = gr < M ? gr : (M - 1);
            cpa16(base + doff,               Ahi + (size_t)grc * K + colb, szA);
            cpa16(base + PIECE*2 + doff,     Alo + (size_t)grc * K + colb, szA);
            /* B pieces */
            int gc = col0 + r;
            int szB = (gc < N) ? 16 : 0;
            int gcc = gc < N ? gc : (N - 1);
            cpa16(base + 2*PIECE*2 + doff,   Bhi + (size_t)gcc * K + colb, szB);
            cpa16(base + 3*PIECE*2 + doff,   Blo + (size_t)gcc * K + colb, szB);
        }
        cpa_commit();
    };

    stage(0, 0);
    for (int ch = 0; ch < nch; ch++) {
        if (ch + 1 < nch) { stage((ch + 1) & 1, ch + 1); cpa_wait1(); }
        else cpa_wait0();
        __syncthreads();
        const uint32_t sb = smb + (ch & 1) * 4 * PIECE * 2;
        const uint32_t pAhi = sb, pAlo = sb + PIECE*2;
        const uint32_t pBhi = sb + 2*PIECE*2, pBlo = sb + 3*PIECE*2;
        #pragma unroll
        for (int ks = 0; ks < 2; ks++) {
            const int kb = ks << 4;
            uint32_t fAh[4][4], fAl[4][4], fBh[2][4], fBl[2][4];
            #pragma unroll
            for (int mt = 0; mt < 4; mt++) {
                uint32_t eo = 2u * ((wr*64 + mt*16) * SSTR + kb + aOff);
                ldm4(pAhi + eo, fAh[mt][0], fAh[mt][1], fAh[mt][2], fAh[mt][3]);
                ldm4(pAlo + eo, fAl[mt][0], fAl[mt][1], fAl[mt][2], fAl[mt][3]);
            }
            #pragma unroll
            for (int np = 0; np < 2; np++) {
                uint32_t eo = 2u * ((wc*32 + np*16) * SSTR + kb + bOff);
                ldm4(pBhi + eo, fBh[np][0], fBh[np][1], fBh[np][2], fBh[np][3]);
                ldm4(pBlo + eo, fBl[np][0], fBl[np][1], fBl[np][2], fBl[np][3]);
            }
            #pragma unroll
            for (int mt = 0; mt < 4; mt++)
                #pragma unroll
                for (int nt = 0; nt < 4; nt++) {
                    const int np = nt >> 1, o = (nt & 1) << 1;
                    mma16816(acc[mt][nt], fAh[mt][0], fAh[mt][1], fAh[mt][2], fAh[mt][3],
                             fBh[np][o], fBh[np][o+1]);
                    mma16816(acc[mt][nt], fAh[mt][0], fAh[mt][1], fAh[mt][2], fAh[mt][3],
                             fBl[np][o], fBl[np][o+1]);
                    mma16816(acc[mt][nt], fAl[mt][0], fAl[mt][1], fAl[mt][2], fAl[mt][3],
                             fBh[np][o], fBh[np][o+1]);
                }
        }
        __syncthreads();
    }

    /* ---- epilogue ---- */
    #pragma unroll
    for (int mt = 0; mt < 4; mt++) {
        int r0 = row0 + wr*64 + mt*16 + g;
        #pragma unroll
        for (int nt = 0; nt < 4; nt++) {
            int cb = col0 + wc*32 + nt*8 + 2*t;
            #pragma unroll
            for (int e = 0; e < 4; e++) {
                int r = r0 + (e >> 1) * 8;
                int c = cb + (e & 1);
                if (r < M && c < N) {
                    float v = acc[mt][nt][e] + bias[c];
                    if (EPI == 1) {
                        v = 0.5f * v * (1.f + erff(v * 0.70710678118f));
                        split_store(Chi, Clo, (size_t)r * N + c, v);
                    } else {
                        if (EPI == 2) v += res[(size_t)r * N + c];
                        C[(size_t)r * N + c] = v;
                    }
                }
            }
        }
    }
}

/* ---------------- patch gather -> bf16 hi/lo xp[B,196,768] ---------------- */
__global__ void k_patch_gather(const float* __restrict__ x,
                               __nv_bfloat16* __restrict__ xhi,
                               __nv_bfloat16* __restrict__ xlo) {
    int idx = blockIdx.x * blockDim.x + threadIdx.x;
    if (idx >= PTOK_*D_) return;
    int k = idx % D_;
    int p = (idx / D_) % NPATCH_;
    int b = idx / (D_ * NPATCH_);
    int c  = k >> 8;
    int iy = (k >> 4) & 15;
    int ix = k & 15;
    int py = p / 14, px = p % 14;
    float v = x[(((size_t)b*3 + c)*224 + py*16 + iy)*224 + px*16 + ix];
    split_store(xhi, xlo, idx, v);
}

/* ---------------- assemble t = [cls | pe] + pos ---------------- */
__global__ void k_assemble(const float* __restrict__ pe, const float* __restrict__ cls,
                           const float* __restrict__ pos, float* __restrict__ t) {
    int idx = blockIdx.x * blockDim.x + threadIdx.x;
    if (idx >= TOK_*D_) return;
    int d = idx % D_;
    int n = (idx / D_) % N_;
    int b = idx / (D_ * N_);
    float v = (n == 0) ? cls[d] : pe[((size_t)b*NPATCH_ + (n-1))*D_ + d];
    t[idx] = v + pos[(size_t)n*D_ + d];
}

/* ---------------- layernorm -> bf16 hi/lo, row length 768 ---------------- */
__global__ void k_layernorm(const float* __restrict__ in, const float* __restrict__ g,
                            const float* __restrict__ b,
                            __nv_bfloat16* __restrict__ ohi, __nv_bfloat16* __restrict__ olo,
                            size_t in_stride) {
    int row = blockIdx.x;
    const float* p = in + (size_t)row * in_stride;
    int t = threadIdx.x;
    float x0 = p[t], x1 = p[t+256], x2 = p[t+512];
    float s  = x0 + x1 + x2;
    float ss = x0*x0 + x1*x1 + x2*x2;
    __shared__ float rs[8], rss[8];
    for (int o = 16; o; o >>= 1) {
        s  += __shfl_xor_sync(0xffffffffu, s,  o);
        ss += __shfl_xor_sync(0xffffffffu, ss, o);
    }
    if ((t & 31) == 0) { rs[t>>5] = s; rss[t>>5] = ss; }
    __syncthreads();
    if (t < 8) { s = rs[t]; ss = rss[t]; }
    else       { s = 0.f;  ss = 0.f; }
    if (t < 32) {
        for (int o = 4; o; o >>= 1) {
            s  += __shfl_xor_sync(0xffffffffu, s,  o);
            ss += __shfl_xor_sync(0xffffffffu, ss, o);
        }
        if (t == 0) { rs[0] = s; rss[0] = ss; }
    }
    __syncthreads();
    float mean = rs[0] * (1.f/768.f);
    float var  = rss[0] * (1.f/768.f) - mean*mean;
    float inv  = rsqrtf(var + 1e-6f);
    size_t base = (size_t)row * D_;
    split_store(ohi, olo, base + t,     (x0 - mean) * inv * g[t]     + b[t]);
    split_store(ohi, olo, base + t+256, (x1 - mean) * inv * g[t+256] + b[t+256]);
    split_store(ohi, olo, base + t+512, (x2 - mean) * inv * g[t+512] + b[t+512]);
}

/* ---------------- attention scores: a[b,h,n,m] = scale * q.k ---------------- */
__global__ void k_attn_scores(const float* __restrict__ qkv, float* __restrict__ a) {
    int bh = blockIdx.z;
    int b = bh / H_, h = bh % H_;
    int n0 = blockIdx.y * 32, m0 = blockIdx.x * 32;
    __shared__ float Qs[32][64];
    __shared__ float Ks[32][64];
    const float* qb = qkv + (size_t)b * N_ * QKVD_ + h * HD_;
    for (int i = threadIdx.x; i < 32*64; i += 256) {
        int r = i >> 6, c = i & 63;
        int n = n0 + r;
        Qs[r][c] = (n < N_) ? qb[(size_t)n*QKVD_ + c] : 0.f;
        int m = m0 + r;
        Ks[r][c] = (m < N_) ? qb[(size_t)m*QKVD_ + D_ + c] : 0.f;
    }
    __syncthreads();
    int ty = threadIdx.x >> 4, tx = threadIdx.x & 15;
    float acc[2][2] = {};
    #pragma unroll
    for (int k = 0; k < 64; k++) {
        float q0 = Qs[ty*2][k],   q1 = Qs[ty*2+1][k];
        float kk0 = Ks[tx*2][k],  kk1 = Ks[tx*2+1][k];
        acc[0][0] += q0*kk0; acc[0][1] += q0*kk1;
        acc[1][0] += q1*kk0; acc[1][1] += q1*kk1;
    }
    float* ab = a + (size_t)bh * NN_;
    #pragma unroll
    for (int i = 0; i < 2; i++)
        #pragma unroll
        for (int j = 0; j < 2; j++) {
            int n = n0 + ty*2 + i, m = m0 + tx*2 + j;
            if (n < N_ && m < N_) ab[(size_t)n*N_ + m] = acc[i][j] * SCALE_;
        }
}

/* ---------------- fused pre-mix + softmax + post-mix, in place ----------------
   block per (b, n): works on a[b, :, n, :] (12 x 197)                          */
__global__ void __launch_bounds__(256)
k_mix_softmax(float* __restrict__ a, const float* __restrict__ wpre,
              const float* __restrict__ wpost) {
    int b = blockIdx.x / N_, n = blockIdx.x % N_;
    __shared__ float sm_[H_][208];
    __shared__ float ws1[H_*H_], ws2[H_*H_];
    int tid = threadIdx.x, wid = tid >> 5, lane = tid & 31;
    if (tid < H_*H_) { ws1[tid] = wpre[tid]; ws2[tid] = wpost[tid]; }
    __syncthreads();
    float* base = a + (size_t)b * H_ * NN_ + (size_t)n * N_;
    if (tid < N_) {
        float vals[H_];
        #pragma unroll
        for (int h = 0; h < H_; h++) vals[h] = base[(size_t)h * NN_ + tid];
        #pragma unroll
        for (int g = 0; g < H_; g++) {
            float s = 0.f;
            #pragma unroll
            for (int h = 0; h < H_; h++) s += ws1[g*H_ + h] * vals[h];
            sm_[g][tid] = s;
        }
    }
    __syncthreads();
    for (int r = wid; r < H_; r += 8) {
        float v[7];
        float mx = -1e30f;
        #pragma unroll
        for (int i = 0; i < 7; i++) {
            int c = lane + i*32;
            v[i] = (c < N_) ? sm_[r][c] : -1e30f;
            mx = fmaxf(mx, v[i]);
        }
        for (int o = 16; o; o >>= 1) mx = fmaxf(mx, __shfl_xor_sync(0xffffffffu, mx, o));
        float s = 0.f;
        #pragma unroll
        for (int i = 0; i < 7; i++) {
            int c = lane + i*32;
            v[i] = (c < N_) ? __expf(v[i] - mx) : 0.f;
            s += v[i];
        }
        for (int o = 16; o; o >>= 1) s += __shfl_xor_sync(0xffffffffu, s, o);
        float inv = 1.f / s;
        #pragma unroll
        for (int i = 0; i < 7; i++) {
            int c = lane + i*32;
            if (c < N_) sm_[r][c] = v[i] * inv;
        }
    }
    __syncthreads();
    if (tid < N_) {
        float vals[H_];
        #pragma unroll
        for (int h = 0; h < H_; h++) vals[h] = sm_[h][tid];
        #pragma unroll
        for (int g = 0; g < H_; g++) {
            float s = 0.f;
            #pragma unroll
            for (int h = 0; h < H_; h++) s += ws2[g*H_ + h] * vals[h];
            base[(size_t)g * NN_ + tid] = s;
        }
    }
}

/* ---------------- AV: o (bf16 hi/lo) = a @ v ---------------- */
__global__ void k_attn_av(const float* __restrict__ a, const float* __restrict__ qkv,
                          __nv_bfloat16* __restrict__ ohi, __nv_bfloat16* __restrict__ olo) {
    int bh = blockIdx.z;
    int b = bh / H_, h = bh % H_;
    int n0 = blockIdx.x * 32;
    const float* ab = a + (size_t)bh * NN_;
    const float* vb = qkv + (size_t)b * N_ * QKVD_ + 2*D_ + h * HD_;
    __shared__ float As[32][33];
    __shared__ float Vs[32][64];
    int ty = threadIdx.x >> 4, tx = threadIdx.x & 15;
    float acc[2][4] = {};
    for (int m0 = 0; m0 < N_; m0 += 32) {
        for (int i = threadIdx.x; i < 32*32; i += 256) {
            int r = i >> 5, c = i & 31;
            int n = n0 + r, m = m0 + c;
            As[r][c] = (n < N_ && m < N_) ? ab[(size_t)n*N_ + m] : 0.f;
        }
        for (int i = threadIdx.x; i < 32*64; i += 256) {
            int r = i >> 6, c = i & 63;
            int m = m0 + r;
            Vs[r][c] = (m < N_) ? vb[(size_t)m*QKVD_ + c] : 0.f;
        }
        __syncthreads();
        #pragma unroll
        for (int k = 0; k < 32; k++) {
            float a0 = As[ty*2][k], a1 = As[ty*2+1][k];
            float4 vv = *reinterpret_cast<const float4*>(&Vs[k][tx*4]);
            float v4[4] = {vv.x, vv.y, vv.z, vv.w};
            #pragma unroll
            for (int j = 0; j < 4; j++) { acc[0][j] += a0 * v4[j]; acc[1][j] += a1 * v4[j]; }
        }
        __syncthreads();
    }
    size_t ob = (size_t)b * N_ * D_ + h * HD_;
    #pragma unroll
    for (int i = 0; i < 2; i++) {
        int n = n0 + ty*2 + i;
        if (n >= N_) continue;
        #pragma unroll
        for (int j = 0; j < 4; j++)
            split_store(ohi, olo, ob + (size_t)n*D_ + tx*4 + j, acc[i][j]);
    }
}

/* ---------------- launch ---------------- */
static inline void* sym(const void* s) { void* p; cudaGetSymbolAddress(&p, s); return p; }

extern "C" void kernel_launch(void* const* d_in, const int* in_sizes, int n_in,
                              void* d_out, int out_size) {
    const float* x      = (const float*)d_in[0];
    const float* Wpe    = (const float*)d_in[1];
    const float* bpe    = (const float*)d_in[2];
    const float* cls    = (const float*)d_in[3];
    const float* pos    = (const float*)d_in[4];
    const float* ln1_g  = (const float*)d_in[5];
    const float* ln1_b  = (const float*)d_in[6];
    const float* qkv_w  = (const float*)d_in[7];
    const float* qkv_b  = (const float*)d_in[8];
    const float* pre_w  = (const float*)d_in[9];
    const float* post_w = (const float*)d_in[10];
    const float* proj_w = (const float*)d_in[11];
    const float* proj_b = (const float*)d_in[12];
    const float* ln2_g  = (const float*)d_in[13];
    const float* ln2_b  = (const float*)d_in[14];
    const float* fc1_w  = (const float*)d_in[15];
    const float* fc1_b  = (const float*)d_in[16];
    const float* fc2_w  = (const float*)d_in[17];
    const float* fc2_b  = (const float*)d_in[18];
    const float* lnf_g  = (const float*)d_in[19];
    const float* lnf_b  = (const float*)d_in[20];
    const float* head_w = (const float*)d_in[21];
    const float* head_b = (const float*)d_in[22];
    float* out = (float*)d_out;

    float* pe  = (float*)sym(g_pe);
    float* t   = (float*)sym(g_t);
    float* qkv = (float*)sym(g_qkv);
    float* a   = (float*)sym(g_a);
    __nv_bfloat16* whi = (__nv_bfloat16*)sym(g_whi);
    __nv_bfloat16* wlo = (__nv_bfloat16*)sym(g_wlo);
    __nv_bfloat16* xhi = (__nv_bfloat16*)sym(g_xhi);
    __nv_bfloat16* xlo = (__nv_bfloat16*)sym(g_xlo);
    __nv_bfloat16* mhi = (__nv_bfloat16*)sym(g_mhi);
    __nv_bfloat16* mlo = (__nv_bfloat16*)sym(g_mlo);

    cudaFuncSetAttribute(k_gemm_bf<0>, cudaFuncAttributeMaxDynamicSharedMemorySize, GSMEM);
    cudaFuncSetAttribute(k_gemm_bf<1>, cudaFuncAttributeMaxDynamicSharedMemorySize, GSMEM);
    cudaFuncSetAttribute(k_gemm_bf<2>, cudaFuncAttributeMaxDynamicSharedMemorySize, GSMEM);

    /* patch embed */
    k_patch_gather<<<(PTOK_*D_ + 255)/256, 256>>>(x, xhi, xlo);
    k_split<<<(768*768/4 + 255)/256, 256>>>(Wpe, whi, wlo, 768*768/4);
    {
        dim3 g((D_+127)/128, (PTOK_+127)/128);
        k_gemm_bf<0><<<g, 256, GSMEM>>>(xhi, xlo, whi, wlo, bpe, nullptr,
                                        pe, nullptr, nullptr, PTOK_, D_, D_);
    }
    k_assemble<<<(TOK_*D_ + 255)/256, 256>>>(pe, cls, pos, t);

    for (int L = 0; L < DEPTH_; L++) {
        const float* l1g = ln1_g + L*D_;
        const float* l1b = ln1_b + L*D_;
        const float* qw  = qkv_w + (size_t)L*QKVD_*D_;
        const float* qb  = qkv_b + L*QKVD_;
        const float* wpr = pre_w  + L*H_*H_;
        const float* wpo = post_w + L*H_*H_;
        const float* pw  = proj_w + (size_t)L*D_*D_;
        const float* pb  = proj_b + L*D_;
        const float* l2g = ln2_g + L*D_;
        const float* l2b = ln2_b + L*D_;
        const float* f1w = fc1_w + (size_t)L*MLP_*D_;
        const float* f1b = fc1_b + L*MLP_;
        const float* f2w = fc2_w + (size_t)L*D_*MLP_;
        const float* f2b = fc2_b + L*D_;

        k_layernorm<<<TOK_, 256>>>(t, l1g, l1b, xhi, xlo, D_);
        k_split<<<(QKVD_*D_/4 + 255)/256, 256>>>(qw, whi, wlo, QKVD_*D_/4);
        {
            dim3 g((QKVD_+127)/128, (TOK_+127)/128);
            k_gemm_bf<0><<<g, 256, GSMEM>>>(xhi, xlo, whi, wlo, qb, nullptr,
                                            qkv, nullptr, nullptr, TOK_, QKVD_, D_);
        }
        {
            dim3 g((N_+31)/32, (N_+31)/32, B_*H_);
            k_attn_scores<<<g, 256>>>(qkv, a);
        }
        k_mix_softmax<<<B_*N_, 256>>>(a, wpr, wpo);
        {
            dim3 g((N_+31)/32, 1, B_*H_);
            k_attn_av<<<g, 256>>>(a, qkv, mhi, mlo);
        }
        k_split<<<(D_*D_/4 + 255)/256, 256>>>(pw, whi, wlo, D_*D_/4);
        {
            dim3 g((D_+127)/128, (TOK_+127)/128);
            k_gemm_bf<2><<<g, 256, GSMEM>>>(mhi, mlo, whi, wlo, pb, t,
                                            t, nullptr, nullptr, TOK_, D_, D_);
        }
        k_layernorm<<<TOK_, 256>>>(t, l2g, l2b, xhi, xlo, D_);
        k_split<<<(MLP_*D_/4 + 255)/256, 256>>>(f1w, whi, wlo, MLP_*D_/4);
        {
            dim3 g((MLP_+127)/128, (TOK_+127)/128);
            k_gemm_bf<1><<<g, 256, GSMEM>>>(xhi, xlo, whi, wlo, f1b, nullptr,
                                            nullptr, mhi, mlo, TOK_, MLP_, D_);
        }
        k_split<<<(D_*MLP_/4 + 255)/256, 256>>>(f2w, whi, wlo, D_*MLP_/4);
        {
            dim3 g((D_+127)/128, (TOK_+127)/128);
            k_gemm_bf<2><<<g, 256, GSMEM>>>(mhi, mlo, whi, wlo, f2b, t,
                                            t, nullptr, nullptr, TOK_, D_, MLP_);
        }
    }

    /* final LN on cls rows only, then head */
    k_layernorm<<<B_, 256>>>(t, lnf_g, lnf_b, xhi, xlo, (size_t)N_*D_);
    k_split<<<(1000*768/4 + 255)/256, 256>>>(head_w, whi, wlo, 1000*768/4);
    {
        dim3 g((1000+127)/128, (B_+127)/128);
        k_gemm_bf<0><<<g, 256, GSMEM>>>(xhi, xlo, whi, wlo, head_b, nullptr,
                                        out, nullptr, nullptr, B_, 1000, D_);
    }
}

// round 11
// speedup vs baseline: 9.0219x; 3.0084x over previous
#include <cuda_runtime.h>
#include <cuda_fp16.h>
#include <cstdint>
#include <math.h>

#define B_     32
#define N_     197
#define D_     768
#define H_     12
#define HD_    64
#define DEPTH_ 12
#define MLP_   3072
#define QKVD_  2304
#define NPATCH_ 196
#define NN_    (N_*N_)
#define TOK_   (B_*N_)          /* 6304 */
#define PTOK_  (B_*NPATCH_)     /* 6272 */
#define SCALE_ 0.125f
#define KPAD_  224              /* padded attention K dim (multiple of 32) */

/* ---------------- scratch (no allocations allowed) ---------------- */
__device__ float g_pe [PTOK_*D_];
__device__ float g_t  [TOK_*D_];
__device__ float g_a  [B_*H_*NN_];
/* fp16 weights (converted once per launch) */
__device__ __align__(16) __half g_wpe [D_*768];
__device__ __align__(16) __half g_wqkv[DEPTH_*QKVD_*D_];
__device__ __align__(16) __half g_wprj[DEPTH_*D_*D_];
__device__ __align__(16) __half g_wfc1[DEPTH_*MLP_*D_];
__device__ __align__(16) __half g_wfc2[DEPTH_*D_*MLP_];
__device__ __align__(16) __half g_whd [1000*D_];
/* fp16 activations */
__device__ __align__(16) __half g_xh[TOK_*D_];          /* patch tokens / LN out / cls */
__device__ __align__(16) __half g_qh[B_*H_*N_*HD_];
__device__ __align__(16) __half g_kh[B_*H_*N_*HD_];
__device__ __align__(16) __half g_vt[B_*H_*HD_*KPAD_]; /* V^T, [bh][d][m] */
__device__ __align__(16) __half g_af[B_*H_*N_*KPAD_];  /* attn post-mix, zero-padded */
__device__ __align__(16) __half g_oh[TOK_*D_];
__device__ __align__(16) __half g_mh[TOK_*MLP_];

/* ================= helpers ================= */
__device__ __forceinline__ uint32_t smem_u32(const void* p) {
    uint32_t a;
    asm("{ .reg .u64 t; cvta.to.shared.u64 t, %1; cvt.u32.u64 %0, t; }" : "=r"(a) : "l"(p));
    return a;
}
__device__ __forceinline__ void mma16816(float* c,
                                         uint32_t a0, uint32_t a1, uint32_t a2, uint32_t a3,
                                         uint32_t b0, uint32_t b1) {
    asm volatile("mma.sync.aligned.m16n8k16.row.col.f32.f16.f16.f32 "
        "{%0,%1,%2,%3}, {%4,%5,%6,%7}, {%8,%9}, {%0,%1,%2,%3};"
        : "+f"(c[0]), "+f"(c[1]), "+f"(c[2]), "+f"(c[3])
        : "r"(a0), "r"(a1), "r"(a2), "r"(a3), "r"(b0), "r"(b1));
}
__device__ __forceinline__ void ldm4(uint32_t addr, uint32_t& r0, uint32_t& r1,
                                     uint32_t& r2, uint32_t& r3) {
    asm volatile("ldmatrix.sync.aligned.m8n8.x4.shared.b16 {%0,%1,%2,%3}, [%4];"
        : "=r"(r0), "=r"(r1), "=r"(r2), "=r"(r3) : "r"(addr));
}
__device__ __forceinline__ void cpa16(uint32_t dst, const void* src, int sz) {
    asm volatile("cp.async.cg.shared.global [%0], [%1], 16, %2;" :: "r"(dst), "l"(src), "r"(sz));
}
__device__ __forceinline__ void cpa_commit() { asm volatile("cp.async.commit_group;" ::: "memory"); }
__device__ __forceinline__ void cpa_wait1()  { asm volatile("cp.async.wait_group 1;" ::: "memory"); }
__device__ __forceinline__ void cpa_wait0()  { asm volatile("cp.async.wait_group 0;" ::: "memory"); }

/* ================= bulk fp32 -> fp16 convert ================= */
__global__ void k_convert(const float* __restrict__ s, __half* __restrict__ d, int n4) {
    int i = blockIdx.x * blockDim.x + threadIdx.x;
    if (i >= n4) return;
    float4 v = reinterpret_cast<const float4*>(s)[i];
    __half2 p0 = __floats2half2_rn(v.x, v.y);
    __half2 p1 = __floats2half2_rn(v.z, v.w);
    reinterpret_cast<__half2*>(d)[2*i]   = p0;
    reinterpret_cast<__half2*>(d)[2*i+1] = p1;
}
__global__ void k_zero_h(__half* __restrict__ p, int n) {
    int i = blockIdx.x * blockDim.x + threadIdx.x;
    if (i < n) p[i] = __float2half(0.f);
}

/* ================= fp16 single-pass HMMA GEMM =================
   C = A[M,K] * W[N,K]^T (+epilogue). CTA 128x128, K chunk 32, 2-stage cp.async,
   256 threads (8 warps 2x4, warp tile 64x32). Batched via blockIdx.z.
   EPI: 0 fp32 +bias | 1 fp16 gelu(+bias) | 2 fp32 +bias+res | 3 fp32 *SCALE_
        5 fp16 plain | 6 qkv scatter (+bias) to g_qh/g_kh/g_vt                  */
#define SSTR 40
#define PC_ELEM (128*SSTR)
#define PC_BYTES (PC_ELEM*2)
#define STAGE_BYTES (2*PC_BYTES)

template<int EPI>
__global__ void __launch_bounds__(256, 2)
k_hgemm(const __half* __restrict__ A, const __half* __restrict__ W,
        const float* __restrict__ bias, const float* __restrict__ res,
        float* __restrict__ C, __half* __restrict__ Ch,
        int M, int N, int K, int lda, int ldb, int ldc,
        int zdiv, long long sAq, long long sAr, long long sBq, long long sBr,
        long long sCq, long long sCr) {
    __shared__ __align__(16) uint16_t sm[2*2*PC_ELEM];
    const int tid = threadIdx.x;
    const int wid = tid >> 5, lane = tid & 31;
    const int g = lane >> 2, t = lane & 3;
    const int wr = wid >> 2, wc = wid & 3;
    const int row0 = blockIdx.y * 128, col0 = blockIdx.x * 128;
    const uint32_t smb = smem_u32(sm);

    const int z = blockIdx.z;
    const int zq = z / zdiv, zr = z - zq * zdiv;
    A += zq * sAq + zr * sAr;
    W += zq * sBq + zr * sBr;
    const long long cbase = zq * sCq + zr * sCr;

    const int l8 = lane & 7, sel = lane >> 3;
    const int aOff = (((sel & 1) << 3) + l8) * SSTR + ((sel & 2) << 2);
    const int bOff = (((sel >> 1) << 3) + l8) * SSTR + ((sel & 1) << 3);

    float acc[4][4][4];
    #pragma unroll
    for (int i = 0; i < 4; i++)
        #pragma unroll
        for (int j = 0; j < 4; j++)
            #pragma unroll
            for (int e = 0; e < 4; e++) acc[i][j][e] = 0.f;

    const int nch = K >> 5;
    auto stage = [&](int stg, int ck) {
        const int k0 = ck << 5;
        const uint32_t base = smb + stg * STAGE_BYTES;
        #pragma unroll
        for (int half = 0; half < 2; half++) {
            int s = tid + (half << 8);
            int r = s >> 2, q = s & 3;
            uint32_t doff = (uint32_t)(r * SSTR + q * 8) * 2;
            int col = k0 + q * 8;
            int gr = row0 + r;
            cpa16(base + doff, A + (size_t)(gr < M ? gr : M-1) * lda + col, (gr < M) ? 16 : 0);
            int gc = col0 + r;
            cpa16(base + PC_BYTES + doff, W + (size_t)(gc < N ? gc : N-1) * ldb + col, (gc < N) ? 16 : 0);
        }
        cpa_commit();
    };

    stage(0, 0);
    for (int ch = 0; ch < nch; ch++) {
        if (ch + 1 < nch) { stage((ch + 1) & 1, ch + 1); cpa_wait1(); }
        else cpa_wait0();
        __syncthreads();
        const uint32_t pA = smb + (ch & 1) * STAGE_BYTES;
        const uint32_t pB = pA + PC_BYTES;
        #pragma unroll
        for (int ks = 0; ks < 2; ks++) {
            const int kb = ks << 4;
            uint32_t fA[4][4], fB[2][4];
            #pragma unroll
            for (int mt = 0; mt < 4; mt++) {
                uint32_t eo = 2u * ((wr*64 + mt*16) * SSTR + kb + aOff);
                ldm4(pA + eo, fA[mt][0], fA[mt][1], fA[mt][2], fA[mt][3]);
            }
            #pragma unroll
            for (int np = 0; np < 2; np++) {
                uint32_t eo = 2u * ((wc*32 + np*16) * SSTR + kb + bOff);
                ldm4(pB + eo, fB[np][0], fB[np][1], fB[np][2], fB[np][3]);
            }
            #pragma unroll
            for (int mt = 0; mt < 4; mt++)
                #pragma unroll
                for (int nt = 0; nt < 4; nt++) {
                    const int np = nt >> 1, o = (nt & 1) << 1;
                    mma16816(acc[mt][nt], fA[mt][0], fA[mt][1], fA[mt][2], fA[mt][3],
                             fB[np][o], fB[np][o+1]);
                }
        }
        __syncthreads();
    }

    /* ---- epilogue ---- */
    #pragma unroll
    for (int mt = 0; mt < 4; mt++) {
        int r0e = row0 + wr*64 + mt*16 + g;
        #pragma unroll
        for (int nt = 0; nt < 4; nt++) {
            int cb = col0 + wc*32 + nt*8 + 2*t;
            #pragma unroll
            for (int e = 0; e < 4; e++) {
                int r = r0e + ((e >> 1) << 3);
                int c = cb + (e & 1);
                if (r < M && c < N) {
                    float v = acc[mt][nt][e];
                    if (EPI == 0) {
                        C[cbase + (size_t)r*ldc + c] = v + bias[c];
                    } else if (EPI == 1) {
                        v += bias[c];
                        v = 0.5f * v * (1.f + erff(v * 0.70710678118f));
                        Ch[cbase + (size_t)r*ldc + c] = __float2half(v);
                    } else if (EPI == 2) {
                        C[cbase + (size_t)r*ldc + c] = v + bias[c] + res[cbase + (size_t)r*ldc + c];
                    } else if (EPI == 3) {
                        C[cbase + (size_t)r*ldc + c] = v * SCALE_;
                    } else if (EPI == 5) {
                        Ch[cbase + (size_t)r*ldc + c] = __float2half(v);
                    } else { /* EPI 6: qkv scatter */
                        int b  = r / N_, n = r - b * N_;
                        int ty = c / D_; int rem = c - ty * D_;
                        int hh = rem >> 6, d = rem & 63;
                        __half hv = __float2half(v + bias[c]);
                        size_t bh = (size_t)(b * H_ + hh);
                        if (ty == 0)      g_qh[(bh * N_ + n) * HD_ + d] = hv;
                        else if (ty == 1) g_kh[(bh * N_ + n) * HD_ + d] = hv;
                        else              g_vt[(bh * HD_ + d) * KPAD_ + n] = hv;
                    }
                }
            }
        }
    }
}

/* ---------------- patch gather -> fp16 tokens [B,196,768] ---------------- */
__global__ void k_patch_gather(const float* __restrict__ x, __half* __restrict__ xh) {
    int idx = blockIdx.x * blockDim.x + threadIdx.x;
    if (idx >= PTOK_*D_) return;
    int k = idx % D_;
    int p = (idx / D_) % NPATCH_;
    int b = idx / (D_ * NPATCH_);
    int c  = k >> 8;
    int iy = (k >> 4) & 15;
    int ix = k & 15;
    int py = p / 14, px = p % 14;
    xh[idx] = __float2half(x[(((size_t)b*3 + c)*224 + py*16 + iy)*224 + px*16 + ix]);
}

/* ---------------- assemble t = [cls | pe] + pos (fp32) ---------------- */
__global__ void k_assemble(const float* __restrict__ pe, const float* __restrict__ cls,
                           const float* __restrict__ pos, float* __restrict__ t) {
    int idx = blockIdx.x * blockDim.x + threadIdx.x;
    if (idx >= TOK_*D_) return;
    int d = idx % D_;
    int n = (idx / D_) % N_;
    int b = idx / (D_ * N_);
    float v = (n == 0) ? cls[d] : pe[((size_t)b*NPATCH_ + (n-1))*D_ + d];
    t[idx] = v + pos[(size_t)n*D_ + d];
}

/* ---------------- layernorm fp32 -> fp16 ---------------- */
__global__ void k_layernorm(const float* __restrict__ in, const float* __restrict__ g,
                            const float* __restrict__ b, __half* __restrict__ out,
                            size_t in_stride) {
    int row = blockIdx.x;
    const float* p = in + (size_t)row * in_stride;
    int t = threadIdx.x;
    float x0 = p[t], x1 = p[t+256], x2 = p[t+512];
    float s  = x0 + x1 + x2;
    float ss = x0*x0 + x1*x1 + x2*x2;
    __shared__ float rs[8], rss[8];
    for (int o = 16; o; o >>= 1) {
        s  += __shfl_xor_sync(0xffffffffu, s,  o);
        ss += __shfl_xor_sync(0xffffffffu, ss, o);
    }
    if ((t & 31) == 0) { rs[t>>5] = s; rss[t>>5] = ss; }
    __syncthreads();
    if (t < 8) { s = rs[t]; ss = rss[t]; }
    else       { s = 0.f;  ss = 0.f; }
    if (t < 32) {
        for (int o = 4; o; o >>= 1) {
            s  += __shfl_xor_sync(0xffffffffu, s,  o);
            ss += __shfl_xor_sync(0xffffffffu, ss, o);
        }
        if (t == 0) { rs[0] = s; rss[0] = ss; }
    }
    __syncthreads();
    float mean = rs[0] * (1.f/768.f);
    float var  = rss[0] * (1.f/768.f) - mean*mean;
    float inv  = rsqrtf(var + 1e-6f);
    size_t base = (size_t)row * D_;
    out[base + t]     = __float2half((x0 - mean) * inv * g[t]     + b[t]);
    out[base + t+256] = __float2half((x1 - mean) * inv * g[t+256] + b[t+256]);
    out[base + t+512] = __float2half((x2 - mean) * inv * g[t+512] + b[t+512]);
}

/* ---------------- fused pre-mix + softmax + post-mix -> fp16 padded ---------------- */
__global__ void __launch_bounds__(256)
k_mix_softmax(const float* __restrict__ a, const float* __restrict__ wpre,
              const float* __restrict__ wpost, __half* __restrict__ af) {
    int b = blockIdx.x / N_, n = blockIdx.x % N_;
    __shared__ float sm_[H_][208];
    __shared__ float ws1[H_*H_], ws2[H_*H_];
    int tid = threadIdx.x, wid = tid >> 5, lane = tid & 31;
    if (tid < H_*H_) { ws1[tid] = wpre[tid]; ws2[tid] = wpost[tid]; }
    __syncthreads();
    if (tid < N_) {
        float vals[H_];
        #pragma unroll
        for (int h = 0; h < H_; h++)
            vals[h] = a[((size_t)(b*H_ + h) * N_ + n) * N_ + tid];
        #pragma unroll
        for (int gg = 0; gg < H_; gg++) {
            float s = 0.f;
            #pragma unroll
            for (int h = 0; h < H_; h++) s += ws1[gg*H_ + h] * vals[h];
            sm_[gg][tid] = s;
        }
    }
    __syncthreads();
    for (int r = wid; r < H_; r += 8) {
        float v[7];
        float mx = -1e30f;
        #pragma unroll
        for (int i = 0; i < 7; i++) {
            int c = lane + i*32;
            v[i] = (c < N_) ? sm_[r][c] : -1e30f;
            mx = fmaxf(mx, v[i]);
        }
        for (int o = 16; o; o >>= 1) mx = fmaxf(mx, __shfl_xor_sync(0xffffffffu, mx, o));
        float s = 0.f;
        #pragma unroll
        for (int i = 0; i < 7; i++) {
            int c = lane + i*32;
            v[i] = (c < N_) ? __expf(v[i] - mx) : 0.f;
            s += v[i];
        }
        for (int o = 16; o; o >>= 1) s += __shfl_xor_sync(0xffffffffu, s, o);
        float inv = 1.f / s;
        #pragma unroll
        for (int i = 0; i < 7; i++) {
            int c = lane + i*32;
            if (c < N_) sm_[r][c] = v[i] * inv;
        }
    }
    __syncthreads();
    if (tid < N_) {
        float vals[H_];
        #pragma unroll
        for (int h = 0; h < H_; h++) vals[h] = sm_[h][tid];
        #pragma unroll
        for (int gg = 0; gg < H_; gg++) {
            float s = 0.f;
            #pragma unroll
            for (int h = 0; h < H_; h++) s += ws2[gg*H_ + h] * vals[h];
            af[((size_t)(b*H_ + gg) * N_ + n) * KPAD_ + tid] = __float2half(s);
        }
    } else if (tid < KPAD_) {
        #pragma unroll
        for (int gg = 0; gg < H_; gg++)
            af[((size_t)(b*H_ + gg) * N_ + n) * KPAD_ + tid] = __float2half(0.f);
    }
}

/* ---------------- launch ---------------- */
static inline void* sym(const void* s) { void* p; cudaGetSymbolAddress(&p, s); return p; }

extern "C" void kernel_launch(void* const* d_in, const int* in_sizes, int n_in,
                              void* d_out, int out_size) {
    const float* x      = (const float*)d_in[0];
    const float* Wpe    = (const float*)d_in[1];
    const float* bpe    = (const float*)d_in[2];
    const float* cls    = (const float*)d_in[3];
    const float* pos    = (const float*)d_in[4];
    const float* ln1_g  = (const float*)d_in[5];
    const float* ln1_b  = (const float*)d_in[6];
    const float* qkv_w  = (const float*)d_in[7];
    const float* qkv_b  = (const float*)d_in[8];
    const float* pre_w  = (const float*)d_in[9];
    const float* post_w = (const float*)d_in[10];
    const float* proj_w = (const float*)d_in[11];
    const float* proj_b = (const float*)d_in[12];
    const float* ln2_g  = (const float*)d_in[13];
    const float* ln2_b  = (const float*)d_in[14];
    const float* fc1_w  = (const float*)d_in[15];
    const float* fc1_b  = (const float*)d_in[16];
    const float* fc2_w  = (const float*)d_in[17];
    const float* fc2_b  = (const float*)d_in[18];
    const float* lnf_g  = (const float*)d_in[19];
    const float* lnf_b  = (const float*)d_in[20];
    const float* head_w = (const float*)d_in[21];
    const float* head_b = (const float*)d_in[22];
    float* out = (float*)d_out;

    float* pe = (float*)sym(g_pe);
    float* t  = (float*)sym(g_t);
    float* a  = (float*)sym(g_a);
    __half* wpeh = (__half*)sym(g_wpe);
    __half* wqkv = (__half*)sym(g_wqkv);
    __half* wprj = (__half*)sym(g_wprj);
    __half* wfc1 = (__half*)sym(g_wfc1);
    __half* wfc2 = (__half*)sym(g_wfc2);
    __half* whd  = (__half*)sym(g_whd);
    __half* xh = (__half*)sym(g_xh);
    __half* af = (__half*)sym(g_af);
    __half* oh = (__half*)sym(g_oh);
    __half* mh = (__half*)sym(g_mh);
    __half* vt = (__half*)sym(g_vt);

    /* weight conversion (once per launch, all layers) */
    {
        int n4;
        n4 = D_*768/4;             k_convert<<<(n4+255)/256, 256>>>(Wpe, wpeh, n4);
        n4 = DEPTH_*QKVD_*D_/4;    k_convert<<<(n4+255)/256, 256>>>(qkv_w, wqkv, n4);
        n4 = DEPTH_*D_*D_/4;       k_convert<<<(n4+255)/256, 256>>>(proj_w, wprj, n4);
        n4 = DEPTH_*MLP_*D_/4;     k_convert<<<(n4+255)/256, 256>>>(fc1_w, wfc1, n4);
        n4 = DEPTH_*D_*MLP_/4;     k_convert<<<(n4+255)/256, 256>>>(fc2_w, wfc2, n4);
        n4 = 1000*D_/4;            k_convert<<<(n4+255)/256, 256>>>(head_w, whd, n4);
        int nv = B_*H_*HD_*KPAD_;  k_zero_h<<<(nv+255)/256, 256>>>(vt, nv);
    }

    /* patch embed */
    k_patch_gather<<<(PTOK_*D_ + 255)/256, 256>>>(x, xh);
    k_hgemm<0><<<dim3(6, 49, 1), 256>>>(xh, wpeh, bpe, nullptr, pe, nullptr,
                                        PTOK_, D_, D_, D_, D_, D_, 1, 0,0,0,0,0,0);
    k_assemble<<<(TOK_*D_ + 255)/256, 256>>>(pe, cls, pos, t);

    for (int L = 0; L < DEPTH_; L++) {
        const float* l1g = ln1_g + L*D_;
        const float* l1b = ln1_b + L*D_;
        const __half* qw = wqkv + (size_t)L*QKVD_*D_;
        const float* qb  = qkv_b + L*QKVD_;
        const float* wpr = pre_w  + L*H_*H_;
        const float* wpo = post_w + L*H_*H_;
        const __half* pw = wprj + (size_t)L*D_*D_;
        const float* pb  = proj_b + L*D_;
        const float* l2g = ln2_g + L*D_;
        const float* l2b = ln2_b + L*D_;
        const __half* f1w = wfc1 + (size_t)L*MLP_*D_;
        const float* f1b = fc1_b + L*MLP_;
        const __half* f2w = wfc2 + (size_t)L*D_*MLP_;
        const float* f2b = fc2_b + L*D_;

        k_layernorm<<<TOK_, 256>>>(t, l1g, l1b, xh, D_);
        /* QKV + scatter to per-head Q, K, V^T */
        k_hgemm<6><<<dim3(18, 50, 1), 256>>>(xh, qw, qb, nullptr, nullptr, nullptr,
                                             TOK_, QKVD_, D_, D_, D_, 0, 1, 0,0,0,0,0,0);
        /* scores = Q K^T * scale  (batched over bh) */
        k_hgemm<3><<<dim3(2, 2, B_*H_), 256>>>(
            (const __half*)sym(g_qh), (const __half*)sym(g_kh), nullptr, nullptr,
            a, nullptr, N_, N_, HD_, HD_, HD_, N_,
            1, (long long)N_*HD_, 0, (long long)N_*HD_, 0, (long long)NN_, 0);
        k_mix_softmax<<<B_*N_, 256>>>(a, wpr, wpo, af);
        /* O = A V  (batched over bh, K padded to 224) */
        k_hgemm<5><<<dim3(1, 2, B_*H_), 256>>>(
            af, vt, nullptr, nullptr, nullptr, oh,
            N_, HD_, KPAD_, KPAD_, KPAD_, D_,
            H_, (long long)H_*N_*KPAD_, (long long)N_*KPAD_,
            (long long)H_*HD_*KPAD_, (long long)HD_*KPAD_,
            (long long)N_*D_, (long long)HD_);
        /* proj + residual */
        k_hgemm<2><<<dim3(6, 50, 1), 256>>>(oh, pw, pb, t, t, nullptr,
                                            TOK_, D_, D_, D_, D_, D_, 1, 0,0,0,0,0,0);
        k_layernorm<<<TOK_, 256>>>(t, l2g, l2b, xh, D_);
        /* fc1 + GELU -> fp16 */
        k_hgemm<1><<<dim3(24, 50, 1), 256>>>(xh, f1w, f1b, nullptr, nullptr, mh,
                                             TOK_, MLP_, D_, D_, D_, MLP_, 1, 0,0,0,0,0,0);
        /* fc2 + residual */
        k_hgemm<2><<<dim3(6, 50, 1), 256>>>(mh, f2w, f2b, t, t, nullptr,
                                            TOK_, D_, MLP_, MLP_, MLP_, D_, 1, 0,0,0,0,0,0);
    }

    /* final LN on cls rows only, then head */
    k_layernorm<<<B_, 256>>>(t, lnf_g, lnf_b, xh, (size_t)N_*D_);
    k_hgemm<0><<<dim3(8, 1, 1), 256>>>(xh, whd, head_b, nullptr, out, nullptr,
                                       B_, 1000, D_, D_, D_, 1000, 1, 0,0,0,0,0,0);
}

// round 12
// speedup vs baseline: 9.1441x; 1.0135x over previous
#include <cuda_runtime.h>
#include <cuda_fp16.h>
#include <cstdint>
#include <math.h>

#define B_     32
#define N_     197
#define D_     768
#define H_     12
#define HD_    64
#define DEPTH_ 12
#define MLP_   3072
#define QKVD_  2304
#define NPATCH_ 196
#define NN_    (N_*N_)
#define TOK_   (B_*N_)          /* 6304 */
#define PTOK_  (B_*NPATCH_)     /* 6272 */
#define SCALE_ 0.125f
#define KPAD_  224              /* padded attention K dim (multiple of 32) */

/* ---------------- scratch (no allocations allowed) ---------------- */
__device__ float g_pe [PTOK_*D_];
__device__ float g_t  [TOK_*D_];
__device__ float g_a  [B_*H_*NN_];
__device__ float g_sk [4*TOK_*D_];                      /* split-K partials */
/* fp16 weights (converted once per launch) */
__device__ __align__(16) __half g_wpe [D_*768];
__device__ __align__(16) __half g_wqkv[DEPTH_*QKVD_*D_];
__device__ __align__(16) __half g_wprj[DEPTH_*D_*D_];
__device__ __align__(16) __half g_wfc1[DEPTH_*MLP_*D_];
__device__ __align__(16) __half g_wfc2[DEPTH_*D_*MLP_];
__device__ __align__(16) __half g_whd [1000*D_];
/* fp16 activations */
__device__ __align__(16) __half g_xh[TOK_*D_];          /* patch tokens / LN out / cls */
__device__ __align__(16) __half g_qh[B_*H_*N_*HD_];
__device__ __align__(16) __half g_kh[B_*H_*N_*HD_];
__device__ __align__(16) __half g_vt[B_*H_*HD_*KPAD_]; /* V^T, [bh][d][m] */
__device__ __align__(16) __half g_af[B_*H_*N_*KPAD_];  /* attn post-mix, zero-padded */
__device__ __align__(16) __half g_oh[TOK_*D_];
__device__ __align__(16) __half g_mh[TOK_*MLP_];

/* ================= helpers ================= */
__device__ __forceinline__ uint32_t smem_u32(const void* p) {
    uint32_t a;
    asm("{ .reg .u64 t; cvta.to.shared.u64 t, %1; cvt.u32.u64 %0, t; }" : "=r"(a) : "l"(p));
    return a;
}
__device__ __forceinline__ void mma16816(float* c,
                                         uint32_t a0, uint32_t a1, uint32_t a2, uint32_t a3,
                                         uint32_t b0, uint32_t b1) {
    asm volatile("mma.sync.aligned.m16n8k16.row.col.f32.f16.f16.f32 "
        "{%0,%1,%2,%3}, {%4,%5,%6,%7}, {%8,%9}, {%0,%1,%2,%3};"
        : "+f"(c[0]), "+f"(c[1]), "+f"(c[2]), "+f"(c[3])
        : "r"(a0), "r"(a1), "r"(a2), "r"(a3), "r"(b0), "r"(b1));
}
__device__ __forceinline__ void ldm4(uint32_t addr, uint32_t& r0, uint32_t& r1,
                                     uint32_t& r2, uint32_t& r3) {
    asm volatile("ldmatrix.sync.aligned.m8n8.x4.shared.b16 {%0,%1,%2,%3}, [%4];"
        : "=r"(r0), "=r"(r1), "=r"(r2), "=r"(r3) : "r"(addr));
}
__device__ __forceinline__ void cpa16(uint32_t dst, const void* src, int sz) {
    asm volatile("cp.async.cg.shared.global [%0], [%1], 16, %2;" :: "r"(dst), "l"(src), "r"(sz));
}
__device__ __forceinline__ void cpa_commit() { asm volatile("cp.async.commit_group;" ::: "memory"); }
__device__ __forceinline__ void cpa_wait1()  { asm volatile("cp.async.wait_group 1;" ::: "memory"); }
__device__ __forceinline__ void cpa_wait0()  { asm volatile("cp.async.wait_group 0;" ::: "memory"); }

/* ================= bulk fp32 -> fp16 convert ================= */
__global__ void k_convert(const float* __restrict__ s, __half* __restrict__ d, int n4) {
    int i = blockIdx.x * blockDim.x + threadIdx.x;
    if (i >= n4) return;
    float4 v = reinterpret_cast<const float4*>(s)[i];
    __half2 p0 = __floats2half2_rn(v.x, v.y);
    __half2 p1 = __floats2half2_rn(v.z, v.w);
    reinterpret_cast<__half2*>(d)[2*i]   = p0;
    reinterpret_cast<__half2*>(d)[2*i+1] = p1;
}
__global__ void k_zero_h(__half* __restrict__ p, int n) {
    int i = blockIdx.x * blockDim.x + threadIdx.x;
    if (i < n) p[i] = __float2half(0.f);
}

/* ================= split-K reduction: dst = [dst +] bias + sum(partials) ============ */
template<int ADD>
__global__ void k_skred(float* __restrict__ dst, const float* __restrict__ p,
                        const float* __restrict__ bias, int n4, int ncols,
                        long long pstride4, int nsplit) {
    int i = blockIdx.x * blockDim.x + threadIdx.x;
    if (i >= n4) return;
    int c = (i * 4) % ncols;
    float4 b = *reinterpret_cast<const float4*>(bias + c);
    float sx = b.x, sy = b.y, sz = b.z, sw = b.w;
    const float4* pp = reinterpret_cast<const float4*>(p);
    for (int s = 0; s < nsplit; s++) {
        float4 v = pp[i + s * pstride4];
        sx += v.x; sy += v.y; sz += v.z; sw += v.w;
    }
    float4 o;
    if (ADD) {
        float4 tv = reinterpret_cast<float4*>(dst)[i];
        o = make_float4(tv.x + sx, tv.y + sy, tv.z + sz, tv.w + sw);
    } else {
        o = make_float4(sx, sy, sz, sw);
    }
    reinterpret_cast<float4*>(dst)[i] = o;
}

/* ================= fp16 single-pass HMMA GEMM =================
   C = A[M,K] * W[N,K]^T (+epilogue). CTA 128x128, K chunk 32, 2-stage cp.async,
   256 threads (8 warps 2x4, warp tile 64x32). Batched via blockIdx.z.
   EPI: 0 fp32 +bias | 1 fp16 gelu(+bias) | 2 fp32 +bias+res | 3 fp32 *SCALE_
        5 fp16 plain | 6 qkv scatter (+bias) | 7 fp32 raw partial (split-K)     */
#define SSTR 40
#define PC_ELEM (128*SSTR)
#define PC_BYTES (PC_ELEM*2)
#define STAGE_BYTES (2*PC_BYTES)

template<int EPI>
__global__ void __launch_bounds__(256, 2)
k_hgemm(const __half* __restrict__ A, const __half* __restrict__ W,
        const float* __restrict__ bias, const float* __restrict__ res,
        float* __restrict__ C, __half* __restrict__ Ch,
        int M, int N, int K, int lda, int ldb, int ldc,
        int zdiv, long long sAq, long long sAr, long long sBq, long long sBr,
        long long sCq, long long sCr) {
    __shared__ __align__(16) uint16_t sm[2*2*PC_ELEM];
    const int tid = threadIdx.x;
    const int wid = tid >> 5, lane = tid & 31;
    const int g = lane >> 2, t = lane & 3;
    const int wr = wid >> 2, wc = wid & 3;
    const int row0 = blockIdx.y * 128, col0 = blockIdx.x * 128;
    const uint32_t smb = smem_u32(sm);

    const int z = blockIdx.z;
    const int zq = z / zdiv, zr = z - zq * zdiv;
    A += zq * sAq + zr * sAr;
    W += zq * sBq + zr * sBr;
    const long long cbase = zq * sCq + zr * sCr;

    const int l8 = lane & 7, sel = lane >> 3;
    const int aOff = (((sel & 1) << 3) + l8) * SSTR + ((sel & 2) << 2);
    const int bOff = (((sel >> 1) << 3) + l8) * SSTR + ((sel & 1) << 3);

    float acc[4][4][4];
    #pragma unroll
    for (int i = 0; i < 4; i++)
        #pragma unroll
        for (int j = 0; j < 4; j++)
            #pragma unroll
            for (int e = 0; e < 4; e++) acc[i][j][e] = 0.f;

    const int nch = K >> 5;
    auto stage = [&](int stg, int ck) {
        const int k0 = ck << 5;
        const uint32_t base = smb + stg * STAGE_BYTES;
        #pragma unroll
        for (int half = 0; half < 2; half++) {
            int s = tid + (half << 8);
            int r = s >> 2, q = s & 3;
            uint32_t doff = (uint32_t)(r * SSTR + q * 8) * 2;
            int col = k0 + q * 8;
            int gr = row0 + r;
            cpa16(base + doff, A + (size_t)(gr < M ? gr : M-1) * lda + col, (gr < M) ? 16 : 0);
            int gc = col0 + r;
            cpa16(base + PC_BYTES + doff, W + (size_t)(gc < N ? gc : N-1) * ldb + col, (gc < N) ? 16 : 0);
        }
        cpa_commit();
    };

    stage(0, 0);
    for (int ch = 0; ch < nch; ch++) {
        if (ch + 1 < nch) { stage((ch + 1) & 1, ch + 1); cpa_wait1(); }
        else cpa_wait0();
        __syncthreads();
        const uint32_t pA = smb + (ch & 1) * STAGE_BYTES;
        const uint32_t pB = pA + PC_BYTES;
        #pragma unroll
        for (int ks = 0; ks < 2; ks++) {
            const int kb = ks << 4;
            uint32_t fA[4][4], fB[2][4];
            #pragma unroll
            for (int mt = 0; mt < 4; mt++) {
                uint32_t eo = 2u * ((wr*64 + mt*16) * SSTR + kb + aOff);
                ldm4(pA + eo, fA[mt][0], fA[mt][1], fA[mt][2], fA[mt][3]);
            }
            #pragma unroll
            for (int np = 0; np < 2; np++) {
                uint32_t eo = 2u * ((wc*32 + np*16) * SSTR + kb + bOff);
                ldm4(pB + eo, fB[np][0], fB[np][1], fB[np][2], fB[np][3]);
            }
            #pragma unroll
            for (int mt = 0; mt < 4; mt++)
                #pragma unroll
                for (int nt = 0; nt < 4; nt++) {
                    const int np = nt >> 1, o = (nt & 1) << 1;
                    mma16816(acc[mt][nt], fA[mt][0], fA[mt][1], fA[mt][2], fA[mt][3],
                             fB[np][o], fB[np][o+1]);
                }
        }
        __syncthreads();
    }

    /* ---- epilogue ---- */
    #pragma unroll
    for (int mt = 0; mt < 4; mt++) {
        int r0e = row0 + wr*64 + mt*16 + g;
        #pragma unroll
        for (int nt = 0; nt < 4; nt++) {
            int cb = col0 + wc*32 + nt*8 + 2*t;
            #pragma unroll
            for (int e = 0; e < 4; e++) {
                int r = r0e + ((e >> 1) << 3);
                int c = cb + (e & 1);
                if (r < M && c < N) {
                    float v = acc[mt][nt][e];
                    if (EPI == 0) {
                        C[cbase + (size_t)r*ldc + c] = v + bias[c];
                    } else if (EPI == 1) {
                        v += bias[c];
                        v = 0.5f * v * (1.f + erff(v * 0.70710678118f));
                        Ch[cbase + (size_t)r*ldc + c] = __float2half(v);
                    } else if (EPI == 2) {
                        C[cbase + (size_t)r*ldc + c] = v + bias[c] + res[cbase + (size_t)r*ldc + c];
                    } else if (EPI == 3) {
                        C[cbase + (size_t)r*ldc + c] = v * SCALE_;
                    } else if (EPI == 5) {
                        Ch[cbase + (size_t)r*ldc + c] = __float2half(v);
                    } else if (EPI == 7) {
                        C[cbase + (size_t)r*ldc + c] = v;
                    } else { /* EPI 6: qkv scatter */
                        int b  = r / N_, n = r - b * N_;
                        int ty = c / D_; int rem = c - ty * D_;
                        int hh = rem >> 6, d = rem & 63;
                        __half hv = __float2half(v + bias[c]);
                        size_t bh = (size_t)(b * H_ + hh);
                        if (ty == 0)      g_qh[(bh * N_ + n) * HD_ + d] = hv;
                        else if (ty == 1) g_kh[(bh * N_ + n) * HD_ + d] = hv;
                        else              g_vt[(bh * HD_ + d) * KPAD_ + n] = hv;
                    }
                }
            }
        }
    }
}

/* ---------------- patch gather -> fp16 tokens [B,196,768] ---------------- */
__global__ void k_patch_gather(const float* __restrict__ x, __half* __restrict__ xh) {
    int idx = blockIdx.x * blockDim.x + threadIdx.x;
    if (idx >= PTOK_*D_) return;
    int k = idx % D_;
    int p = (idx / D_) % NPATCH_;
    int b = idx / (D_ * NPATCH_);
    int c  = k >> 8;
    int iy = (k >> 4) & 15;
    int ix = k & 15;
    int py = p / 14, px = p % 14;
    xh[idx] = __float2half(x[(((size_t)b*3 + c)*224 + py*16 + iy)*224 + px*16 + ix]);
}

/* ---------------- assemble t = [cls | pe] + pos (fp32) ---------------- */
__global__ void k_assemble(const float* __restrict__ pe, const float* __restrict__ cls,
                           const float* __restrict__ pos, float* __restrict__ t) {
    int idx = blockIdx.x * blockDim.x + threadIdx.x;
    if (idx >= TOK_*D_) return;
    int d = idx % D_;
    int n = (idx / D_) % N_;
    int b = idx / (D_ * N_);
    float v = (n == 0) ? cls[d] : pe[((size_t)b*NPATCH_ + (n-1))*D_ + d];
    t[idx] = v + pos[(size_t)n*D_ + d];
}

/* ---------------- layernorm fp32 -> fp16 ---------------- */
__global__ void k_layernorm(const float* __restrict__ in, const float* __restrict__ g,
                            const float* __restrict__ b, __half* __restrict__ out,
                            size_t in_stride) {
    int row = blockIdx.x;
    const float* p = in + (size_t)row * in_stride;
    int t = threadIdx.x;
    float x0 = p[t], x1 = p[t+256], x2 = p[t+512];
    float s  = x0 + x1 + x2;
    float ss = x0*x0 + x1*x1 + x2*x2;
    __shared__ float rs[8], rss[8];
    for (int o = 16; o; o >>= 1) {
        s  += __shfl_xor_sync(0xffffffffu, s,  o);
        ss += __shfl_xor_sync(0xffffffffu, ss, o);
    }
    if ((t & 31) == 0) { rs[t>>5] = s; rss[t>>5] = ss; }
    __syncthreads();
    if (t < 8) { s = rs[t]; ss = rss[t]; }
    else       { s = 0.f;  ss = 0.f; }
    if (t < 32) {
        for (int o = 4; o; o >>= 1) {
            s  += __shfl_xor_sync(0xffffffffu, s,  o);
            ss += __shfl_xor_sync(0xffffffffu, ss, o);
        }
        if (t == 0) { rs[0] = s; rss[0] = ss; }
    }
    __syncthreads();
    float mean = rs[0] * (1.f/768.f);
    float var  = rss[0] * (1.f/768.f) - mean*mean;
    float inv  = rsqrtf(var + 1e-6f);
    size_t base = (size_t)row * D_;
    out[base + t]     = __float2half((x0 - mean) * inv * g[t]     + b[t]);
    out[base + t+256] = __float2half((x1 - mean) * inv * g[t+256] + b[t+256]);
    out[base + t+512] = __float2half((x2 - mean) * inv * g[t+512] + b[t+512]);
}

/* ---------------- fused pre-mix + softmax + post-mix -> fp16 padded ---------------- */
__global__ void __launch_bounds__(224)
k_mix_softmax(const float* __restrict__ a, const float* __restrict__ wpre,
              const float* __restrict__ wpost, __half* __restrict__ af) {
    int b = blockIdx.x / N_, n = blockIdx.x % N_;
    __shared__ float sm_[H_][208];
    __shared__ float ws1[H_*H_], ws2[H_*H_];
    int tid = threadIdx.x, wid = tid >> 5, lane = tid & 31;
    if (tid < H_*H_) { ws1[tid] = wpre[tid]; ws2[tid] = wpost[tid]; }
    __syncthreads();
    if (tid < N_) {
        float vals[H_];
        #pragma unroll
        for (int h = 0; h < H_; h++)
            vals[h] = a[((size_t)(b*H_ + h) * N_ + n) * N_ + tid];
        #pragma unroll
        for (int gg = 0; gg < H_; gg++) {
            float s = 0.f;
            #pragma unroll
            for (int h = 0; h < H_; h++) s += ws1[gg*H_ + h] * vals[h];
            sm_[gg][tid] = s;
        }
    }
    __syncthreads();
    for (int r = wid; r < H_; r += 7) {
        float v[7];
        float mx = -1e30f;
        #pragma unroll
        for (int i = 0; i < 7; i++) {
            int c = lane + i*32;
            v[i] = (c < N_) ? sm_[r][c] : -1e30f;
            mx = fmaxf(mx, v[i]);
        }
        for (int o = 16; o; o >>= 1) mx = fmaxf(mx, __shfl_xor_sync(0xffffffffu, mx, o));
        float s = 0.f;
        #pragma unroll
        for (int i = 0; i < 7; i++) {
            int c = lane + i*32;
            v[i] = (c < N_) ? __expf(v[i] - mx) : 0.f;
            s += v[i];
        }
        for (int o = 16; o; o >>= 1) s += __shfl_xor_sync(0xffffffffu, s, o);
        float inv = 1.f / s;
        #pragma unroll
        for (int i = 0; i < 7; i++) {
            int c = lane + i*32;
            if (c < N_) sm_[r][c] = v[i] * inv;
        }
    }
    __syncthreads();
    if (tid < N_) {
        float vals[H_];
        #pragma unroll
        for (int h = 0; h < H_; h++) vals[h] = sm_[h][tid];
        #pragma unroll
        for (int gg = 0; gg < H_; gg++) {
            float s = 0.f;
            #pragma unroll
            for (int h = 0; h < H_; h++) s += ws2[gg*H_ + h] * vals[h];
            af[((size_t)(b*H_ + gg) * N_ + n) * KPAD_ + tid] = __float2half(s);
        }
    } else {
        #pragma unroll
        for (int gg = 0; gg < H_; gg++)
            af[((size_t)(b*H_ + gg) * N_ + n) * KPAD_ + tid] = __float2half(0.f);
    }
}

/* ---------------- launch ---------------- */
static inline void* sym(const void* s) { void* p; cudaGetSymbolAddress(&p, s); return p; }

extern "C" void kernel_launch(void* const* d_in, const int* in_sizes, int n_in,
                              void* d_out, int out_size) {
    const float* x      = (const float*)d_in[0];
    const float* Wpe    = (const float*)d_in[1];
    const float* bpe    = (const float*)d_in[2];
    const float* cls    = (const float*)d_in[3];
    const float* pos    = (const float*)d_in[4];
    const float* ln1_g  = (const float*)d_in[5];
    const float* ln1_b  = (const float*)d_in[6];
    const float* qkv_w  = (const float*)d_in[7];
    const float* qkv_b  = (const float*)d_in[8];
    const float* pre_w  = (const float*)d_in[9];
    const float* post_w = (const float*)d_in[10];
    const float* proj_w = (const float*)d_in[11];
    const float* proj_b = (const float*)d_in[12];
    const float* ln2_g  = (const float*)d_in[13];
    const float* ln2_b  = (const float*)d_in[14];
    const float* fc1_w  = (const float*)d_in[15];
    const float* fc1_b  = (const float*)d_in[16];
    const float* fc2_w  = (const float*)d_in[17];
    const float* fc2_b  = (const float*)d_in[18];
    const float* lnf_g  = (const float*)d_in[19];
    const float* lnf_b  = (const float*)d_in[20];
    const float* head_w = (const float*)d_in[21];
    const float* head_b = (const float*)d_in[22];
    float* out = (float*)d_out;

    float* pe = (float*)sym(g_pe);
    float* t  = (float*)sym(g_t);
    float* a  = (float*)sym(g_a);
    float* sk = (float*)sym(g_sk);
    __half* wpeh = (__half*)sym(g_wpe);
    __half* wqkv = (__half*)sym(g_wqkv);
    __half* wprj = (__half*)sym(g_wprj);
    __half* wfc1 = (__half*)sym(g_wfc1);
    __half* wfc2 = (__half*)sym(g_wfc2);
    __half* whd  = (__half*)sym(g_whd);
    __half* xh = (__half*)sym(g_xh);
    __half* af = (__half*)sym(g_af);
    __half* oh = (__half*)sym(g_oh);
    __half* mh = (__half*)sym(g_mh);
    __half* vt = (__half*)sym(g_vt);

    /* weight conversion (once per launch, all layers) */
    {
        int n4;
        n4 = D_*768/4;             k_convert<<<(n4+255)/256, 256>>>(Wpe, wpeh, n4);
        n4 = DEPTH_*QKVD_*D_/4;    k_convert<<<(n4+255)/256, 256>>>(qkv_w, wqkv, n4);
        n4 = DEPTH_*D_*D_/4;       k_convert<<<(n4+255)/256, 256>>>(proj_w, wprj, n4);
        n4 = DEPTH_*MLP_*D_/4;     k_convert<<<(n4+255)/256, 256>>>(fc1_w, wfc1, n4);
        n4 = DEPTH_*D_*MLP_/4;     k_convert<<<(n4+255)/256, 256>>>(fc2_w, wfc2, n4);
        n4 = 1000*D_/4;            k_convert<<<(n4+255)/256, 256>>>(head_w, whd, n4);
        int nv = B_*H_*HD_*KPAD_;  k_zero_h<<<(nv+255)/256, 256>>>(vt, nv);
    }

    /* patch embed */
    k_patch_gather<<<(PTOK_*D_ + 255)/256, 256>>>(x, xh);
    k_hgemm<0><<<dim3(6, 49, 1), 256>>>(xh, wpeh, bpe, nullptr, pe, nullptr,
                                        PTOK_, D_, D_, D_, D_, D_, 1, 0,0,0,0,0,0);
    k_assemble<<<(TOK_*D_ + 255)/256, 256>>>(pe, cls, pos, t);

    for (int L = 0; L < DEPTH_; L++) {
        const float* l1g = ln1_g + L*D_;
        const float* l1b = ln1_b + L*D_;
        const __half* qw = wqkv + (size_t)L*QKVD_*D_;
        const float* qb  = qkv_b + L*QKVD_;
        const float* wpr = pre_w  + L*H_*H_;
        const float* wpo = post_w + L*H_*H_;
        const __half* pw = wprj + (size_t)L*D_*D_;
        const float* pb  = proj_b + L*D_;
        const float* l2g = ln2_g + L*D_;
        const float* l2b = ln2_b + L*D_;
        const __half* f1w = wfc1 + (size_t)L*MLP_*D_;
        const float* f1b = fc1_b + L*MLP_;
        const __half* f2w = wfc2 + (size_t)L*D_*MLP_;
        const float* f2b = fc2_b + L*D_;

        k_layernorm<<<TOK_, 256>>>(t, l1g, l1b, xh, D_);
        /* QKV + scatter to per-head Q, K, V^T */
        k_hgemm<6><<<dim3(18, 50, 1), 256>>>(xh, qw, qb, nullptr, nullptr, nullptr,
                                             TOK_, QKVD_, D_, D_, D_, 0, 1, 0,0,0,0,0,0);
        /* scores = Q K^T * scale  (batched over bh) */
        k_hgemm<3><<<dim3(2, 2, B_*H_), 256>>>(
            (const __half*)sym(g_qh), (const __half*)sym(g_kh), nullptr, nullptr,
            a, nullptr, N_, N_, HD_, HD_, HD_, N_,
            1, (long long)N_*HD_, 0, (long long)N_*HD_, 0, (long long)NN_, 0);
        k_mix_softmax<<<B_*N_, 224>>>(a, wpr, wpo, af);
        /* O = A V  (batched over bh, K padded to 224) */
        k_hgemm<5><<<dim3(1, 2, B_*H_), 256>>>(
            af, vt, nullptr, nullptr, nullptr, oh,
            N_, HD_, KPAD_, KPAD_, KPAD_, D_,
            H_, (long long)H_*N_*KPAD_, (long long)N_*KPAD_,
            (long long)H_*HD_*KPAD_, (long long)HD_*KPAD_,
            (long long)N_*D_, (long long)HD_);
        /* proj + residual */
        k_hgemm<2><<<dim3(6, 50, 1), 256>>>(oh, pw, pb, t, t, nullptr,
                                            TOK_, D_, D_, D_, D_, D_, 1, 0,0,0,0,0,0);
        k_layernorm<<<TOK_, 256>>>(t, l2g, l2b, xh, D_);
        /* fc1 + GELU -> fp16 */
        k_hgemm<1><<<dim3(24, 50, 1), 256>>>(xh, f1w, f1b, nullptr, nullptr, mh,
                                             TOK_, MLP_, D_, D_, D_, MLP_, 1, 0,0,0,0,0,0);
        /* fc2 split-K=4: partials then deterministic reduce (+bias +residual) */
        k_hgemm<7><<<dim3(6, 50, 4), 256>>>(mh, f2w, nullptr, nullptr, sk, nullptr,
                                            TOK_, D_, MLP_/4, MLP_, MLP_, D_,
                                            4, 0, MLP_/4, 0, MLP_/4, 0, (long long)TOK_*D_);
        k_skred<1><<<(TOK_*D_/4 + 255)/256, 256>>>(t, sk, f2b, TOK_*D_/4, D_,
                                                   (long long)TOK_*D_/4, 4);
    }

    /* final LN on cls rows only, then head (split-K=8) */
    k_layernorm<<<B_, 256>>>(t, lnf_g, lnf_b, xh, (size_t)N_*D_);
    k_hgemm<7><<<dim3(8, 1, 8), 256>>>(xh, whd, nullptr, nullptr, sk, nullptr,
                                       B_, 1000, D_/8, D_, D_, 1000,
                                       8, 0, D_/8, 0, D_/8, 0, (long long)B_*1000);
    k_skred<0><<<(B_*1000/4 + 255)/256, 256>>>(out, sk, head_b, B_*1000/4, 1000,
                                               (long long)B_*1000/4, 8);
}

// round 14
// speedup vs baseline: 9.3527x; 1.0228x over previous
#include <cuda_runtime.h>
#include <cuda_fp16.h>
#include <cstdint>
#include <math.h>

#define B_     32
#define N_     197
#define D_     768
#define H_     12
#define HD_    64
#define DEPTH_ 12
#define MLP_   3072
#define QKVD_  2304
#define NPATCH_ 196
#define NN_    (N_*N_)
#define TOK_   (B_*N_)          /* 6304 */
#define PTOK_  (B_*NPATCH_)     /* 6272 */
#define SCALE_ 0.125f
#define KPAD_  224              /* padded attention K dim (multiple of 32) */

/* ---------------- scratch (no allocations allowed) ---------------- */
__device__ float g_pe [PTOK_*D_];
__device__ float g_t  [TOK_*D_];
__device__ float g_a  [B_*H_*NN_];
__device__ float g_sk [4*TOK_*D_];                      /* split-K partials */
/* fp16 weights (converted once per launch) */
__device__ __align__(16) __half g_wpe [D_*768];
__device__ __align__(16) __half g_wqkv[DEPTH_*QKVD_*D_];
__device__ __align__(16) __half g_wprj[DEPTH_*D_*D_];
__device__ __align__(16) __half g_wfc1[DEPTH_*MLP_*D_];
__device__ __align__(16) __half g_wfc2[DEPTH_*D_*MLP_];
__device__ __align__(16) __half g_whd [1000*D_];
/* fp16 activations */
__device__ __align__(16) __half g_xh[TOK_*D_];          /* patch tokens / LN out / cls */
__device__ __align__(16) __half g_qh[B_*H_*N_*HD_];
__device__ __align__(16) __half g_kh[B_*H_*N_*HD_];
__device__ __align__(16) __half g_vt[B_*H_*HD_*KPAD_]; /* V^T, [bh][d][m] */
__device__ __align__(16) __half g_af[B_*H_*N_*KPAD_];  /* attn post-mix, zero-padded */
__device__ __align__(16) __half g_oh[TOK_*D_];
__device__ __align__(16) __half g_mh[TOK_*MLP_];

/* ================= helpers ================= */
__device__ __forceinline__ uint32_t smem_u32(const void* p) {
    uint32_t a;
    asm("{ .reg .u64 t; cvta.to.shared.u64 t, %1; cvt.u32.u64 %0, t; }" : "=r"(a) : "l"(p));
    return a;
}
__device__ __forceinline__ void mma16816(float* c,
                                         uint32_t a0, uint32_t a1, uint32_t a2, uint32_t a3,
                                         uint32_t b0, uint32_t b1) {
    asm volatile("mma.sync.aligned.m16n8k16.row.col.f32.f16.f16.f32 "
        "{%0,%1,%2,%3}, {%4,%5,%6,%7}, {%8,%9}, {%0,%1,%2,%3};"
        : "+f"(c[0]), "+f"(c[1]), "+f"(c[2]), "+f"(c[3])
        : "r"(a0), "r"(a1), "r"(a2), "r"(a3), "r"(b0), "r"(b1));
}
__device__ __forceinline__ void ldm4(uint32_t addr, uint32_t& r0, uint32_t& r1,
                                     uint32_t& r2, uint32_t& r3) {
    asm volatile("ldmatrix.sync.aligned.m8n8.x4.shared.b16 {%0,%1,%2,%3}, [%4];"
        : "=r"(r0), "=r"(r1), "=r"(r2), "=r"(r3) : "r"(addr));
}
__device__ __forceinline__ void cpa16(uint32_t dst, const void* src, int sz) {
    asm volatile("cp.async.cg.shared.global [%0], [%1], 16, %2;" :: "r"(dst), "l"(src), "r"(sz));
}
__device__ __forceinline__ void cpa_commit() { asm volatile("cp.async.commit_group;" ::: "memory"); }
__device__ __forceinline__ void cpa_wait2()  { asm volatile("cp.async.wait_group 2;" ::: "memory"); }

/* ================= bulk fp32 -> fp16 convert ================= */
__global__ void k_convert(const float* __restrict__ s, __half* __restrict__ d, int n4) {
    int i = blockIdx.x * blockDim.x + threadIdx.x;
    if (i >= n4) return;
    float4 v = reinterpret_cast<const float4*>(s)[i];
    __half2 p0 = __floats2half2_rn(v.x, v.y);
    __half2 p1 = __floats2half2_rn(v.z, v.w);
    reinterpret_cast<__half2*>(d)[2*i]   = p0;
    reinterpret_cast<__half2*>(d)[2*i+1] = p1;
}
__global__ void k_zero_h(__half* __restrict__ p, int n) {
    int i = blockIdx.x * blockDim.x + threadIdx.x;
    if (i < n) p[i] = __float2half(0.f);
}

/* ================= split-K reduction: dst = [dst +] bias + sum(partials) ============ */
template<int ADD>
__global__ void k_skred(float* __restrict__ dst, const float* __restrict__ p,
                        const float* __restrict__ bias, int n4, int ncols,
                        long long pstride4, int nsplit) {
    int i = blockIdx.x * blockDim.x + threadIdx.x;
    if (i >= n4) return;
    int c = (i * 4) % ncols;
    float4 b = *reinterpret_cast<const float4*>(bias + c);
    float sx = b.x, sy = b.y, sz = b.z, sw = b.w;
    const float4* pp = reinterpret_cast<const float4*>(p);
    for (int s = 0; s < nsplit; s++) {
        float4 v = pp[i + s * pstride4];
        sx += v.x; sy += v.y; sz += v.z; sw += v.w;
    }
    float4 o;
    if (ADD) {
        float4 tv = reinterpret_cast<float4*>(dst)[i];
        o = make_float4(tv.x + sx, tv.y + sy, tv.z + sz, tv.w + sw);
    } else {
        o = make_float4(sx, sy, sz, sw);
    }
    reinterpret_cast<float4*>(dst)[i] = o;
}

/* ================= fp16 single-pass HMMA GEMM =================
   C = A[M,K] * W[N,K]^T (+epilogue). CTA 128x128, K chunk 32, 4-stage cp.async
   pipeline with ONE __syncthreads per chunk. 256 threads (8 warps 2x4,
   warp tile 64x32). Batched via blockIdx.z.
   EPI: 0 fp32 +bias | 1 fp16 gelu(+bias) | 2 fp32 +bias+res | 3 fp32 *SCALE_
        5 fp16 plain | 6 qkv scatter (+bias) | 7 fp32 raw partial (split-K)     */
#define SSTR 40
#define PC_ELEM (128*SSTR)
#define PC_BYTES (PC_ELEM*2)
#define STAGE_BYTES (2*PC_BYTES)
#define NSTAGE 4
#define GSMEM (NSTAGE*STAGE_BYTES)      /* 81920 bytes dynamic */

template<int EPI>
__global__ void __launch_bounds__(256, 2)
k_hgemm(const __half* __restrict__ A, const __half* __restrict__ W,
        const float* __restrict__ bias, const float* __restrict__ res,
        float* __restrict__ C, __half* __restrict__ Ch,
        int M, int N, int K, int lda, int ldb, int ldc,
        int zdiv, long long sAq, long long sAr, long long sBq, long long sBr,
        long long sCq, long long sCr) {
    extern __shared__ __align__(16) uint16_t sm[];
    const int tid = threadIdx.x;
    const int wid = tid >> 5, lane = tid & 31;
    const int g = lane >> 2, t = lane & 3;
    const int wr = wid >> 2, wc = wid & 3;
    const int row0 = blockIdx.y * 128, col0 = blockIdx.x * 128;
    const uint32_t smb = smem_u32(sm);

    const int z = blockIdx.z;
    const int zq = z / zdiv, zr = z - zq * zdiv;
    A += zq * sAq + zr * sAr;
    W += zq * sBq + zr * sBr;
    const long long cbase = zq * sCq + zr * sCr;

    const int l8 = lane & 7, sel = lane >> 3;
    const int aOff = (((sel & 1) << 3) + l8) * SSTR + ((sel & 2) << 2);
    const int bOff = (((sel >> 1) << 3) + l8) * SSTR + ((sel & 1) << 3);

    float acc[4][4][4];
    #pragma unroll
    for (int i = 0; i < 4; i++)
        #pragma unroll
        for (int j = 0; j < 4; j++)
            #pragma unroll
            for (int e = 0; e < 4; e++) acc[i][j][e] = 0.f;

    const int nch = K >> 5;
    /* stage chunk ck into buffer ck%4 (empty-commit past the end) */
    auto stage = [&](int ck) {
        const int ok = (ck < nch) ? 1 : 0;
        const int k0 = ok ? (ck << 5) : 0;
        const uint32_t base = smb + (uint32_t)(ck & (NSTAGE-1)) * STAGE_BYTES;
        #pragma unroll
        for (int half = 0; half < 2; half++) {
            int s = tid + (half << 8);
            int r = s >> 2, q = s & 3;
            uint32_t doff = (uint32_t)(r * SSTR + q * 8) * 2;
            int col = k0 + q * 8;
            int gr = row0 + r;
            cpa16(base + doff, A + (size_t)(gr < M ? gr : M-1) * lda + col,
                  (ok && gr < M) ? 16 : 0);
            int gc = col0 + r;
            cpa16(base + PC_BYTES + doff, W + (size_t)(gc < N ? gc : N-1) * ldb + col,
                  (ok && gc < N) ? 16 : 0);
        }
        cpa_commit();
    };

    stage(0); stage(1); stage(2);
    for (int ch = 0; ch < nch; ch++) {
        cpa_wait2();            /* oldest pending (chunk ch) has landed */
        __syncthreads();        /* all lanes see it; all done reading buf (ch-1)%4 */
        stage(ch + 3);          /* overwrite buf (ch-1)%4, overlapped with compute */
        const uint32_t pA = smb + (uint32_t)(ch & (NSTAGE-1)) * STAGE_BYTES;
        const uint32_t pB = pA + PC_BYTES;
        #pragma unroll
        for (int ks = 0; ks < 2; ks++) {
            const int kb = ks << 4;
            uint32_t fA[4][4], fB[2][4];
            #pragma unroll
            for (int mt = 0; mt < 4; mt++) {
                uint32_t eo = 2u * ((wr*64 + mt*16) * SSTR + kb + aOff);
                ldm4(pA + eo, fA[mt][0], fA[mt][1], fA[mt][2], fA[mt][3]);
            }
            #pragma unroll
            for (int np = 0; np < 2; np++) {
                uint32_t eo = 2u * ((wc*32 + np*16) * SSTR + kb + bOff);
                ldm4(pB + eo, fB[np][0], fB[np][1], fB[np][2], fB[np][3]);
            }
            #pragma unroll
            for (int mt = 0; mt < 4; mt++)
                #pragma unroll
                for (int nt = 0; nt < 4; nt++) {
                    const int np = nt >> 1, o = (nt & 1) << 1;
                    mma16816(acc[mt][nt], fA[mt][0], fA[mt][1], fA[mt][2], fA[mt][3],
                             fB[np][o], fB[np][o+1]);
                }
        }
    }

    /* ---- epilogue ---- */
    #pragma unroll
    for (int mt = 0; mt < 4; mt++) {
        int r0e = row0 + wr*64 + mt*16 + g;
        #pragma unroll
        for (int nt = 0; nt < 4; nt++) {
            int cb = col0 + wc*32 + nt*8 + 2*t;
            #pragma unroll
            for (int e = 0; e < 4; e++) {
                int r = r0e + ((e >> 1) << 3);
                int c = cb + (e & 1);
                if (r < M && c < N) {
                    float v = acc[mt][nt][e];
                    if (EPI == 0) {
                        C[cbase + (size_t)r*ldc + c] = v + bias[c];
                    } else if (EPI == 1) {
                        v += bias[c];
                        v = 0.5f * v * (1.f + erff(v * 0.70710678118f));
                        Ch[cbase + (size_t)r*ldc + c] = __float2half(v);
                    } else if (EPI == 2) {
                        C[cbase + (size_t)r*ldc + c] = v + bias[c] + res[cbase + (size_t)r*ldc + c];
                    } else if (EPI == 3) {
                        C[cbase + (size_t)r*ldc + c] = v * SCALE_;
                    } else if (EPI == 5) {
                        Ch[cbase + (size_t)r*ldc + c] = __float2half(v);
                    } else if (EPI == 7) {
                        C[cbase + (size_t)r*ldc + c] = v;
                    } else { /* EPI 6: qkv scatter */
                        int b  = r / N_, n = r - b * N_;
                        int ty = c / D_; int rem = c - ty * D_;
                        int hh = rem >> 6, d = rem & 63;
                        __half hv = __float2half(v + bias[c]);
                        size_t bh = (size_t)(b * H_ + hh);
                        if (ty == 0)      g_qh[(bh * N_ + n) * HD_ + d] = hv;
                        else if (ty == 1) g_kh[(bh * N_ + n) * HD_ + d] = hv;
                        else              g_vt[(bh * HD_ + d) * KPAD_ + n] = hv;
                    }
                }
            }
        }
    }
}

/* ---------------- patch gather -> fp16 tokens [B,196,768] ---------------- */
__global__ void k_patch_gather(const float* __restrict__ x, __half* __restrict__ xh) {
    int idx = blockIdx.x * blockDim.x + threadIdx.x;
    if (idx >= PTOK_*D_) return;
    int k = idx % D_;
    int p = (idx / D_) % NPATCH_;
    int b = idx / (D_ * NPATCH_);
    int c  = k >> 8;
    int iy = (k >> 4) & 15;
    int ix = k & 15;
    int py = p / 14, px = p % 14;
    xh[idx] = __float2half(x[(((size_t)b*3 + c)*224 + py*16 + iy)*224 + px*16 + ix]);
}

/* ---------------- assemble t = [cls | pe] + pos (fp32) ---------------- */
__global__ void k_assemble(const float* __restrict__ pe, const float* __restrict__ cls,
                           const float* __restrict__ pos, float* __restrict__ t) {
    int idx = blockIdx.x * blockDim.x + threadIdx.x;
    if (idx >= TOK_*D_) return;
    int d = idx % D_;
    int n = (idx / D_) % N_;
    int b = idx / (D_ * N_);
    float v = (n == 0) ? cls[d] : pe[((size_t)b*NPATCH_ + (n-1))*D_ + d];
    t[idx] = v + pos[(size_t)n*D_ + d];
}

/* ---------------- layernorm fp32 -> fp16 ---------------- */
__global__ void k_layernorm(const float* __restrict__ in, const float* __restrict__ g,
                            const float* __restrict__ b, __half* __restrict__ out,
                            size_t in_stride) {
    int row = blockIdx.x;
    const float* p = in + (size_t)row * in_stride;
    int t = threadIdx.x;
    float x0 = p[t], x1 = p[t+256], x2 = p[t+512];
    float s  = x0 + x1 + x2;
    float ss = x0*x0 + x1*x1 + x2*x2;
    __shared__ float rs[8], rss[8];
    for (int o = 16; o; o >>= 1) {
        s  += __shfl_xor_sync(0xffffffffu, s,  o);
        ss += __shfl_xor_sync(0xffffffffu, ss, o);
    }
    if ((t & 31) == 0) { rs[t>>5] = s; rss[t>>5] = ss; }
    __syncthreads();
    if (t < 8) { s = rs[t]; ss = rss[t]; }
    else       { s = 0.f;  ss = 0.f; }
    if (t < 32) {
        for (int o = 4; o; o >>= 1) {
            s  += __shfl_xor_sync(0xffffffffu, s,  o);
            ss += __shfl_xor_sync(0xffffffffu, ss, o);
        }
        if (t == 0) { rs[0] = s; rss[0] = ss; }
    }
    __syncthreads();
    float mean = rs[0] * (1.f/768.f);
    float var  = rss[0] * (1.f/768.f) - mean*mean;
    float inv  = rsqrtf(var + 1e-6f);
    size_t base = (size_t)row * D_;
    out[base + t]     = __float2half((x0 - mean) * inv * g[t]     + b[t]);
    out[base + t+256] = __float2half((x1 - mean) * inv * g[t+256] + b[t+256]);
    out[base + t+512] = __float2half((x2 - mean) * inv * g[t+512] + b[t+512]);
}

/* ---------------- fused pre-mix + softmax + post-mix -> fp16 padded ---------------- */
__global__ void __launch_bounds__(224)
k_mix_softmax(const float* __restrict__ a, const float* __restrict__ wpre,
              const float* __restrict__ wpost, __half* __restrict__ af) {
    int b = blockIdx.x / N_, n = blockIdx.x % N_;
    __shared__ float sm_[H_][208];
    __shared__ float ws1[H_*H_], ws2[H_*H_];
    int tid = threadIdx.x, wid = tid >> 5, lane = tid & 31;
    if (tid < H_*H_) { ws1[tid] = wpre[tid]; ws2[tid] = wpost[tid]; }
    __syncthreads();
    if (tid < N_) {
        float vals[H_];
        #pragma unroll
        for (int h = 0; h < H_; h++)
            vals[h] = a[((size_t)(b*H_ + h) * N_ + n) * N_ + tid];
        #pragma unroll
        for (int gg = 0; gg < H_; gg++) {
            float s = 0.f;
            #pragma unroll
            for (int h = 0; h < H_; h++) s += ws1[gg*H_ + h] * vals[h];
            sm_[gg][tid] = s;
        }
    }
    __syncthreads();
    for (int r = wid; r < H_; r += 7) {
        float v[7];
        float mx = -1e30f;
        #pragma unroll
        for (int i = 0; i < 7; i++) {
            int c = lane + i*32;
            v[i] = (c < N_) ? sm_[r][c] : -1e30f;
            mx = fmaxf(mx, v[i]);
        }
        for (int o = 16; o; o >>= 1) mx = fmaxf(mx, __shfl_xor_sync(0xffffffffu, mx, o));
        float s = 0.f;
        #pragma unroll
        for (int i = 0; i < 7; i++) {
            int c = lane + i*32;
            v[i] = (c < N_) ? __expf(v[i] - mx) : 0.f;
            s += v[i];
        }
        for (int o = 16; o; o >>= 1) s += __shfl_xor_sync(0xffffffffu, s, o);
        float inv = 1.f / s;
        #pragma unroll
        for (int i = 0; i < 7; i++) {
            int c = lane + i*32;
            if (c < N_) sm_[r][c] = v[i] * inv;
        }
    }
    __syncthreads();
    if (tid < N_) {
        float vals[H_];
        #pragma unroll
        for (int h = 0; h < H_; h++) vals[h] = sm_[h][tid];
        #pragma unroll
        for (int gg = 0; gg < H_; gg++) {
            float s = 0.f;
            #pragma unroll
            for (int h = 0; h < H_; h++) s += ws2[gg*H_ + h] * vals[h];
            af[((size_t)(b*H_ + gg) * N_ + n) * KPAD_ + tid] = __float2half(s);
        }
    } else {
        #pragma unroll
        for (int gg = 0; gg < H_; gg++)
            af[((size_t)(b*H_ + gg) * N_ + n) * KPAD_ + tid] = __float2half(0.f);
    }
}

/* ---------------- launch ---------------- */
static inline void* sym(const void* s) { void* p; cudaGetSymbolAddress(&p, s); return p; }

extern "C" void kernel_launch(void* const* d_in, const int* in_sizes, int n_in,
                              void* d_out, int out_size) {
    const float* x      = (const float*)d_in[0];
    const float* Wpe    = (const float*)d_in[1];
    const float* bpe    = (const float*)d_in[2];
    const float* cls    = (const float*)d_in[3];
    const float* pos    = (const float*)d_in[4];
    const float* ln1_g  = (const float*)d_in[5];
    const float* ln1_b  = (const float*)d_in[6];
    const float* qkv_w  = (const float*)d_in[7];
    const float* qkv_b  = (const float*)d_in[8];
    const float* pre_w  = (const float*)d_in[9];
    const float* post_w = (const float*)d_in[10];
    const float* proj_w = (const float*)d_in[11];
    const float* proj_b = (const float*)d_in[12];
    const float* ln2_g  = (const float*)d_in[13];
    const float* ln2_b  = (const float*)d_in[14];
    const float* fc1_w  = (const float*)d_in[15];
    const float* fc1_b  = (const float*)d_in[16];
    const float* fc2_w  = (const float*)d_in[17];
    const float* fc2_b  = (const float*)d_in[18];
    const float* lnf_g  = (const float*)d_in[19];
    const float* lnf_b  = (const float*)d_in[20];
    const float* head_w = (const float*)d_in[21];
    const float* head_b = (const float*)d_in[22];
    float* out = (float*)d_out;

    float* pe = (float*)sym(g_pe);
    float* t  = (float*)sym(g_t);
    float* a  = (float*)sym(g_a);
    float* sk = (float*)sym(g_sk);
    __half* wpeh = (__half*)sym(g_wpe);
    __half* wqkv = (__half*)sym(g_wqkv);
    __half* wprj = (__half*)sym(g_wprj);
    __half* wfc1 = (__half*)sym(g_wfc1);
    __half* wfc2 = (__half*)sym(g_wfc2);
    __half* whd  = (__half*)sym(g_whd);
    __half* xh = (__half*)sym(g_xh);
    __half* af = (__half*)sym(g_af);
    __half* oh = (__half*)sym(g_oh);
    __half* mh = (__half*)sym(g_mh);
    __half* vt = (__half*)sym(g_vt);

    cudaFuncSetAttribute(k_hgemm<0>, cudaFuncAttributeMaxDynamicSharedMemorySize, GSMEM);
    cudaFuncSetAttribute(k_hgemm<1>, cudaFuncAttributeMaxDynamicSharedMemorySize, GSMEM);
    cudaFuncSetAttribute(k_hgemm<2>, cudaFuncAttributeMaxDynamicSharedMemorySize, GSMEM);
    cudaFuncSetAttribute(k_hgemm<3>, cudaFuncAttributeMaxDynamicSharedMemorySize, GSMEM);
    cudaFuncSetAttribute(k_hgemm<5>, cudaFuncAttributeMaxDynamicSharedMemorySize, GSMEM);
    cudaFuncSetAttribute(k_hgemm<6>, cudaFuncAttributeMaxDynamicSharedMemorySize, GSMEM);
    cudaFuncSetAttribute(k_hgemm<7>, cudaFuncAttributeMaxDynamicSharedMemorySize, GSMEM);

    /* launches 0-5 ordered so ncu (-s 5) profiles a representative K=768 GEMM */
    { int n4 = D_*768/4;          k_convert<<<(n4+255)/256, 256>>>(Wpe, wpeh, n4); }        /* 0 */
    { int n4 = DEPTH_*QKVD_*D_/4; k_convert<<<(n4+255)/256, 256>>>(qkv_w, wqkv, n4); }      /* 1 */
    { int n4 = DEPTH_*D_*D_/4;    k_convert<<<(n4+255)/256, 256>>>(proj_w, wprj, n4); }     /* 2 */
    { int n4 = DEPTH_*MLP_*D_/4;  k_convert<<<(n4+255)/256, 256>>>(fc1_w, wfc1, n4); }      /* 3 */
    k_patch_gather<<<(PTOK_*D_ + 255)/256, 256>>>(x, xh);                                   /* 4 */
    k_hgemm<0><<<dim3(6, 49, 1), 256, GSMEM>>>(xh, wpeh, bpe, nullptr, pe, nullptr,         /* 5 */
                                               PTOK_, D_, D_, D_, D_, D_, 1, 0,0,0,0,0,0);
    { int n4 = DEPTH_*D_*MLP_/4;  k_convert<<<(n4+255)/256, 256>>>(fc2_w, wfc2, n4); }
    { int n4 = 1000*D_/4;         k_convert<<<(n4+255)/256, 256>>>(head_w, whd, n4); }
    { int nv = B_*H_*HD_*KPAD_;   k_zero_h<<<(nv+255)/256, 256>>>(vt, nv); }
    k_assemble<<<(TOK_*D_ + 255)/256, 256>>>(pe, cls, pos, t);

    for (int L = 0; L < DEPTH_; L++) {
        const float* l1g = ln1_g + L*D_;
        const float* l1b = ln1_b + L*D_;
        const __half* qw = wqkv + (size_t)L*QKVD_*D_;
        const float* qb  = qkv_b + L*QKVD_;
        const float* wpr = pre_w  + L*H_*H_;
        const float* wpo = post_w + L*H_*H_;
        const __half* pw = wprj + (size_t)L*D_*D_;
        const float* pb  = proj_b + L*D_;
        const float* l2g = ln2_g + L*D_;
        const float* l2b = ln2_b + L*D_;
        const __half* f1w = wfc1 + (size_t)L*MLP_*D_;
        const float* f1b = fc1_b + L*MLP_;
        const __half* f2w = wfc2 + (size_t)L*D_*MLP_;
        const float* f2b = fc2_b + L*D_;

        k_layernorm<<<TOK_, 256>>>(t, l1g, l1b, xh, D_);
        /* QKV + scatter to per-head Q, K, V^T */
        k_hgemm<6><<<dim3(18, 50, 1), 256, GSMEM>>>(xh, qw, qb, nullptr, nullptr, nullptr,
                                                    TOK_, QKVD_, D_, D_, D_, 0, 1, 0,0,0,0,0,0);
        /* scores = Q K^T * scale  (batched over bh) */
        k_hgemm<3><<<dim3(2, 2, B_*H_), 256, GSMEM>>>(
            (const __half*)sym(g_qh), (const __half*)sym(g_kh), nullptr, nullptr,
            a, nullptr, N_, N_, HD_, HD_, HD_, N_,
            1, (long long)N_*HD_, 0, (long long)N_*HD_, 0, (long long)NN_, 0);
        k_mix_softmax<<<B_*N_, 224>>>(a, wpr, wpo, af);
        /* O = A V  (batched over bh, K padded to 224) */
        k_hgemm<5><<<dim3(1, 2, B_*H_), 256, GSMEM>>>(
            af, vt, nullptr, nullptr, nullptr, oh,
            N_, HD_, KPAD_, KPAD_, KPAD_, D_,
            H_, (long long)H_*N_*KPAD_, (long long)N_*KPAD_,
            (long long)H_*HD_*KPAD_, (long long)HD_*KPAD_,
            (long long)N_*D_, (long long)HD_);
        /* proj + residual */
        k_hgemm<2><<<dim3(6, 50, 1), 256, GSMEM>>>(oh, pw, pb, t, t, nullptr,
                                                   TOK_, D_, D_, D_, D_, D_, 1, 0,0,0,0,0,0);
        k_layernorm<<<TOK_, 256>>>(t, l2g, l2b, xh, D_);
        /* fc1 + GELU -> fp16 */
        k_hgemm<1><<<dim3(24, 50, 1), 256, GSMEM>>>(xh, f1w, f1b, nullptr, nullptr, mh,
                                                    TOK_, MLP_, D_, D_, D_, MLP_, 1, 0,0,0,0,0,0);
        /* fc2 split-K=4: partials then deterministic reduce (+bias +residual) */
        k_hgemm<7><<<dim3(6, 50, 4), 256, GSMEM>>>(mh, f2w, nullptr, nullptr, sk, nullptr,
                                                   TOK_, D_, MLP_/4, MLP_, MLP_, D_,
                                                   4, 0, MLP_/4, 0, MLP_/4, 0, (long long)TOK_*D_);
        k_skred<1><<<(TOK_*D_/4 + 255)/256, 256>>>(t, sk, f2b, TOK_*D_/4, D_,
                                                   (long long)TOK_*D_/4, 4);
    }

    /* final LN on cls rows only, then head (split-K=8) */
    k_layernorm<<<B_, 256>>>(t, lnf_g, lnf_b, xh, (size_t)N_*D_);
    k_hgemm<7><<<dim3(8, 1, 8), 256, GSMEM>>>(xh, whd, nullptr, nullptr, sk, nullptr,
                                              B_, 1000, D_/8, D_, D_, 1000,
                                              8, 0, D_/8, 0, D_/8, 0, (long long)B_*1000);
    k_skred<0><<<(B_*1000/4 + 255)/256, 256>>>(out, sk, head_b, B_*1000/4, 1000,
                                               (long long)B_*1000/4, 8);
}

// round 15
// speedup vs baseline: 9.5223x; 1.0181x over previous
#include <cuda_runtime.h>
#include <cuda_fp16.h>
#include <cstdint>
#include <math.h>

#define B_     32
#define N_     197
#define D_     768
#define H_     12
#define HD_    64
#define DEPTH_ 12
#define MLP_   3072
#define QKVD_  2304
#define NPATCH_ 196
#define NN_    (N_*N_)
#define TOK_   (B_*N_)          /* 6304 */
#define PTOK_  (B_*NPATCH_)     /* 6272 */
#define SCALE_ 0.125f
#define KPAD_  224              /* padded attention K dim (multiple of 32) */

/* ---------------- scratch (no allocations allowed) ---------------- */
__device__ float g_pe [PTOK_*D_];
__device__ float g_t  [TOK_*D_];
__device__ float g_a  [B_*H_*NN_];
__device__ float g_sk [4*TOK_*D_];                      /* split-K partials */
/* fp16 weights (converted once per launch) */
__device__ __align__(16) __half g_wpe [D_*768];
__device__ __align__(16) __half g_wqkv[DEPTH_*QKVD_*D_];
__device__ __align__(16) __half g_wprj[DEPTH_*D_*D_];
__device__ __align__(16) __half g_wfc1[DEPTH_*MLP_*D_];
__device__ __align__(16) __half g_wfc2[DEPTH_*D_*MLP_];
__device__ __align__(16) __half g_whd [1000*D_];
/* fp16 activations */
__device__ __align__(16) __half g_xh[TOK_*D_];          /* patch tokens / LN out / cls */
__device__ __align__(16) __half g_qh[B_*H_*N_*HD_];
__device__ __align__(16) __half g_kh[B_*H_*N_*HD_];
__device__ __align__(16) __half g_vt[B_*H_*HD_*KPAD_]; /* V^T, [bh][d][m] */
__device__ __align__(16) __half g_af[B_*H_*N_*KPAD_];  /* attn post-mix, zero-padded */
__device__ __align__(16) __half g_oh[TOK_*D_];
__device__ __align__(16) __half g_mh[TOK_*MLP_];

/* ================= helpers ================= */
__device__ __forceinline__ uint32_t smem_u32(const void* p) {
    uint32_t a;
    asm("{ .reg .u64 t; cvta.to.shared.u64 t, %1; cvt.u32.u64 %0, t; }" : "=r"(a) : "l"(p));
    return a;
}
__device__ __forceinline__ void mma16816(float* c,
                                         uint32_t a0, uint32_t a1, uint32_t a2, uint32_t a3,
                                         uint32_t b0, uint32_t b1) {
    asm volatile("mma.sync.aligned.m16n8k16.row.col.f32.f16.f16.f32 "
        "{%0,%1,%2,%3}, {%4,%5,%6,%7}, {%8,%9}, {%0,%1,%2,%3};"
        : "+f"(c[0]), "+f"(c[1]), "+f"(c[2]), "+f"(c[3])
        : "r"(a0), "r"(a1), "r"(a2), "r"(a3), "r"(b0), "r"(b1));
}
__device__ __forceinline__ void ldm4(uint32_t addr, uint32_t& r0, uint32_t& r1,
                                     uint32_t& r2, uint32_t& r3) {
    asm volatile("ldmatrix.sync.aligned.m8n8.x4.shared.b16 {%0,%1,%2,%3}, [%4];"
        : "=r"(r0), "=r"(r1), "=r"(r2), "=r"(r3) : "r"(addr));
}
__device__ __forceinline__ void cpa16(uint32_t dst, const void* src, int sz) {
    asm volatile("cp.async.cg.shared.global [%0], [%1], 16, %2;" :: "r"(dst), "l"(src), "r"(sz));
}
__device__ __forceinline__ void cpa_commit() { asm volatile("cp.async.commit_group;" ::: "memory"); }
__device__ __forceinline__ void cpa_wait2()  { asm volatile("cp.async.wait_group 2;" ::: "memory"); }

/* ================= bulk fp32 -> fp16 convert ================= */
__global__ void k_convert(const float* __restrict__ s, __half* __restrict__ d, int n4) {
    int i = blockIdx.x * blockDim.x + threadIdx.x;
    if (i >= n4) return;
    float4 v = reinterpret_cast<const float4*>(s)[i];
    __half2 p0 = __floats2half2_rn(v.x, v.y);
    __half2 p1 = __floats2half2_rn(v.z, v.w);
    reinterpret_cast<__half2*>(d)[2*i]   = p0;
    reinterpret_cast<__half2*>(d)[2*i+1] = p1;
}
__global__ void k_zero_h(__half* __restrict__ p, int n) {
    int i = blockIdx.x * blockDim.x + threadIdx.x;
    if (i < n) p[i] = __float2half(0.f);
}

/* ================= split-K reduction: dst = [dst +] bias + sum(partials) ============ */
template<int ADD>
__global__ void k_skred(float* __restrict__ dst, const float* __restrict__ p,
                        const float* __restrict__ bias, int n4, int ncols,
                        long long pstride4, int nsplit) {
    int i = blockIdx.x * blockDim.x + threadIdx.x;
    if (i >= n4) return;
    int c = (i * 4) % ncols;
    float4 b = *reinterpret_cast<const float4*>(bias + c);
    float sx = b.x, sy = b.y, sz = b.z, sw = b.w;
    const float4* pp = reinterpret_cast<const float4*>(p);
    for (int s = 0; s < nsplit; s++) {
        float4 v = pp[i + s * pstride4];
        sx += v.x; sy += v.y; sz += v.z; sw += v.w;
    }
    float4 o;
    if (ADD) {
        float4 tv = reinterpret_cast<float4*>(dst)[i];
        o = make_float4(tv.x + sx, tv.y + sy, tv.z + sz, tv.w + sw);
    } else {
        o = make_float4(sx, sy, sz, sw);
    }
    reinterpret_cast<float4*>(dst)[i] = o;
}

/* ================= fused fc2 split-K reduce + residual + next-layer LN ============
   block per token row: t[row] += bias + sum partials; then LN(t[row]) -> xh[row]   */
__global__ void k_skred_ln(float* __restrict__ t, const float* __restrict__ sk,
                           const float* __restrict__ bias,
                           const float* __restrict__ g, const float* __restrict__ b,
                           __half* __restrict__ out) {
    int row = blockIdx.x;
    int tid = threadIdx.x;
    float vv[3];
    #pragma unroll
    for (int i = 0; i < 3; i++) {
        int c = tid + (i << 8);
        float s = bias[c];
        #pragma unroll
        for (int sp = 0; sp < 4; sp++)
            s += sk[(size_t)sp * TOK_ * D_ + (size_t)row * D_ + c];
        float val = t[(size_t)row * D_ + c] + s;
        t[(size_t)row * D_ + c] = val;
        vv[i] = val;
    }
    float s  = vv[0] + vv[1] + vv[2];
    float ss = vv[0]*vv[0] + vv[1]*vv[1] + vv[2]*vv[2];
    __shared__ float rs[8], rss[8];
    for (int o = 16; o; o >>= 1) {
        s  += __shfl_xor_sync(0xffffffffu, s,  o);
        ss += __shfl_xor_sync(0xffffffffu, ss, o);
    }
    if ((tid & 31) == 0) { rs[tid>>5] = s; rss[tid>>5] = ss; }
    __syncthreads();
    if (tid < 8) { s = rs[tid]; ss = rss[tid]; }
    else         { s = 0.f;    ss = 0.f; }
    if (tid < 32) {
        for (int o = 4; o; o >>= 1) {
            s  += __shfl_xor_sync(0xffffffffu, s,  o);
            ss += __shfl_xor_sync(0xffffffffu, ss, o);
        }
        if (tid == 0) { rs[0] = s; rss[0] = ss; }
    }
    __syncthreads();
    float mean = rs[0] * (1.f/768.f);
    float var  = rss[0] * (1.f/768.f) - mean*mean;
    float inv  = rsqrtf(var + 1e-6f);
    size_t base = (size_t)row * D_;
    out[base + tid]     = __float2half((vv[0] - mean) * inv * g[tid]     + b[tid]);
    out[base + tid+256] = __float2half((vv[1] - mean) * inv * g[tid+256] + b[tid+256]);
    out[base + tid+512] = __float2half((vv[2] - mean) * inv * g[tid+512] + b[tid+512]);
}

/* ================= fp16 single-pass HMMA GEMM =================
   C = A[M,K] * W[N,K]^T (+epilogue). CTA 128xNTILE, K chunk 32, 4-stage cp.async,
   one __syncthreads per chunk. 256 threads (8 warps 2x4). Batched via blockIdx.z.
   NTILE=128: warp tile 64x32.  NTILE=64: warp tile 64x16 (half B-stage/MMAs).
   EPI: 0 fp32 +bias | 1 fp16 gelu(+bias) | 2 fp32 +bias+res | 3 fp32 *SCALE_
        5 fp16 plain | 6 qkv scatter (+bias) | 7 fp32 raw partial (split-K)     */
#define SSTR 40
#define PC_ELEM (128*SSTR)
#define PC_BYTES (PC_ELEM*2)
#define STAGE_BYTES (2*PC_BYTES)
#define NSTAGE 4
#define GSMEM (NSTAGE*STAGE_BYTES)      /* 81920 bytes dynamic */

template<int EPI, int NTILE>
__global__ void __launch_bounds__(256, 2)
k_hgemm(const __half* __restrict__ A, const __half* __restrict__ W,
        const float* __restrict__ bias, const float* __restrict__ res,
        float* __restrict__ C, __half* __restrict__ Ch,
        int M, int N, int K, int lda, int ldb, int ldc,
        int zdiv, long long sAq, long long sAr, long long sBq, long long sBr,
        long long sCq, long long sCr) {
    extern __shared__ __align__(16) uint16_t sm[];
    constexpr int NNP = NTILE / 64;     /* B ldmatrix groups per warp */
    constexpr int NNT = NTILE / 32;     /* 8-col output groups per warp */
    const int tid = threadIdx.x;
    const int wid = tid >> 5, lane = tid & 31;
    const int g = lane >> 2, t = lane & 3;
    const int wr = wid >> 2, wc = wid & 3;
    const int row0 = blockIdx.y * 128, col0 = blockIdx.x * NTILE;
    const uint32_t smb = smem_u32(sm);

    const int z = blockIdx.z;
    const int zq = z / zdiv, zr = z - zq * zdiv;
    A += zq * sAq + zr * sAr;
    W += zq * sBq + zr * sBr;
    const long long cbase = zq * sCq + zr * sCr;

    const int l8 = lane & 7, sel = lane >> 3;
    const int aOff = (((sel & 1) << 3) + l8) * SSTR + ((sel & 2) << 2);
    const int bOff = (((sel >> 1) << 3) + l8) * SSTR + ((sel & 1) << 3);

    float acc[4][NNT][4];
    #pragma unroll
    for (int i = 0; i < 4; i++)
        #pragma unroll
        for (int j = 0; j < NNT; j++)
            #pragma unroll
            for (int e = 0; e < 4; e++) acc[i][j][e] = 0.f;

    const int nch = K >> 5;
    auto stage = [&](int ck) {
        const int ok = (ck < nch) ? 1 : 0;
        const int k0 = ok ? (ck << 5) : 0;
        const uint32_t base = smb + (uint32_t)(ck & (NSTAGE-1)) * STAGE_BYTES;
        #pragma unroll
        for (int half = 0; half < 2; half++) {
            int s = tid + (half << 8);
            int r = s >> 2, q = s & 3;
            uint32_t doff = (uint32_t)(r * SSTR + q * 8) * 2;
            int col = k0 + q * 8;
            int gr = row0 + r;
            cpa16(base + doff, A + (size_t)(gr < M ? gr : M-1) * lda + col,
                  (ok && gr < M) ? 16 : 0);
            if (NTILE == 128 || half == 0) {
                int gc = col0 + r;
                cpa16(base + PC_BYTES + doff, W + (size_t)(gc < N ? gc : N-1) * ldb + col,
                      (ok && gc < N) ? 16 : 0);
            }
        }
        cpa_commit();
    };

    stage(0); stage(1); stage(2);
    for (int ch = 0; ch < nch; ch++) {
        cpa_wait2();
        __syncthreads();
        stage(ch + 3);
        const uint32_t pA = smb + (uint32_t)(ch & (NSTAGE-1)) * STAGE_BYTES;
        const uint32_t pB = pA + PC_BYTES;
        #pragma unroll
        for (int ks = 0; ks < 2; ks++) {
            const int kb = ks << 4;
            uint32_t fA[4][4], fB[NNP][4];
            #pragma unroll
            for (int mt = 0; mt < 4; mt++) {
                uint32_t eo = 2u * ((wr*64 + mt*16) * SSTR + kb + aOff);
                ldm4(pA + eo, fA[mt][0], fA[mt][1], fA[mt][2], fA[mt][3]);
            }
            #pragma unroll
            for (int np = 0; np < NNP; np++) {
                uint32_t eo = 2u * ((wc*(NTILE/4) + np*16) * SSTR + kb + bOff);
                ldm4(pB + eo, fB[np][0], fB[np][1], fB[np][2], fB[np][3]);
            }
            #pragma unroll
            for (int mt = 0; mt < 4; mt++)
                #pragma unroll
                for (int nt = 0; nt < NNT; nt++) {
                    const int np = nt >> 1, o = (nt & 1) << 1;
                    mma16816(acc[mt][nt], fA[mt][0], fA[mt][1], fA[mt][2], fA[mt][3],
                             fB[np][o], fB[np][o+1]);
                }
        }
    }

    /* ---- epilogue ---- */
    #pragma unroll
    for (int mt = 0; mt < 4; mt++) {
        int r0e = row0 + wr*64 + mt*16 + g;
        #pragma unroll
        for (int nt = 0; nt < NNT; nt++) {
            int cb = col0 + wc*(NTILE/4) + nt*8 + 2*t;
            #pragma unroll
            for (int e = 0; e < 4; e++) {
                int r = r0e + ((e >> 1) << 3);
                int c = cb + (e & 1);
                if (r < M && c < N) {
                    float v = acc[mt][nt][e];
                    if (EPI == 0) {
                        C[cbase + (size_t)r*ldc + c] = v + bias[c];
                    } else if (EPI == 1) {
                        v += bias[c];
                        v = 0.5f * v * (1.f + erff(v * 0.70710678118f));
                        Ch[cbase + (size_t)r*ldc + c] = __float2half(v);
                    } else if (EPI == 2) {
                        C[cbase + (size_t)r*ldc + c] = v + bias[c] + res[cbase + (size_t)r*ldc + c];
                    } else if (EPI == 3) {
                        C[cbase + (size_t)r*ldc + c] = v * SCALE_;
                    } else if (EPI == 5) {
                        Ch[cbase + (size_t)r*ldc + c] = __float2half(v);
                    } else if (EPI == 7) {
                        C[cbase + (size_t)r*ldc + c] = v;
                    } else { /* EPI 6: qkv scatter */
                        int b  = r / N_, n = r - b * N_;
                        int ty = c / D_; int rem = c - ty * D_;
                        int hh = rem >> 6, d = rem & 63;
                        __half hv = __float2half(v + bias[c]);
                        size_t bh = (size_t)(b * H_ + hh);
                        if (ty == 0)      g_qh[(bh * N_ + n) * HD_ + d] = hv;
                        else if (ty == 1) g_kh[(bh * N_ + n) * HD_ + d] = hv;
                        else              g_vt[(bh * HD_ + d) * KPAD_ + n] = hv;
                    }
                }
            }
        }
    }
}

/* ---------------- patch gather -> fp16 tokens [B,196,768] ---------------- */
__global__ void k_patch_gather(const float* __restrict__ x, __half* __restrict__ xh) {
    int idx = blockIdx.x * blockDim.x + threadIdx.x;
    if (idx >= PTOK_*D_) return;
    int k = idx % D_;
    int p = (idx / D_) % NPATCH_;
    int b = idx / (D_ * NPATCH_);
    int c  = k >> 8;
    int iy = (k >> 4) & 15;
    int ix = k & 15;
    int py = p / 14, px = p % 14;
    xh[idx] = __float2half(x[(((size_t)b*3 + c)*224 + py*16 + iy)*224 + px*16 + ix]);
}

/* ---------------- assemble t = [cls | pe] + pos (fp32) ---------------- */
__global__ void k_assemble(const float* __restrict__ pe, const float* __restrict__ cls,
                           const float* __restrict__ pos, float* __restrict__ t) {
    int idx = blockIdx.x * blockDim.x + threadIdx.x;
    if (idx >= TOK_*D_) return;
    int d = idx % D_;
    int n = (idx / D_) % N_;
    int b = idx / (D_ * N_);
    float v = (n == 0) ? cls[d] : pe[((size_t)b*NPATCH_ + (n-1))*D_ + d];
    t[idx] = v + pos[(size_t)n*D_ + d];
}

/* ---------------- layernorm fp32 -> fp16 ---------------- */
__global__ void k_layernorm(const float* __restrict__ in, const float* __restrict__ g,
                            const float* __restrict__ b, __half* __restrict__ out,
                            size_t in_stride) {
    int row = blockIdx.x;
    const float* p = in + (size_t)row * in_stride;
    int t = threadIdx.x;
    float x0 = p[t], x1 = p[t+256], x2 = p[t+512];
    float s  = x0 + x1 + x2;
    float ss = x0*x0 + x1*x1 + x2*x2;
    __shared__ float rs[8], rss[8];
    for (int o = 16; o; o >>= 1) {
        s  += __shfl_xor_sync(0xffffffffu, s,  o);
        ss += __shfl_xor_sync(0xffffffffu, ss, o);
    }
    if ((t & 31) == 0) { rs[t>>5] = s; rss[t>>5] = ss; }
    __syncthreads();
    if (t < 8) { s = rs[t]; ss = rss[t]; }
    else       { s = 0.f;  ss = 0.f; }
    if (t < 32) {
        for (int o = 4; o; o >>= 1) {
            s  += __shfl_xor_sync(0xffffffffu, s,  o);
            ss += __shfl_xor_sync(0xffffffffu, ss, o);
        }
        if (t == 0) { rs[0] = s; rss[0] = ss; }
    }
    __syncthreads();
    float mean = rs[0] * (1.f/768.f);
    float var  = rss[0] * (1.f/768.f) - mean*mean;
    float inv  = rsqrtf(var + 1e-6f);
    size_t base = (size_t)row * D_;
    out[base + t]     = __float2half((x0 - mean) * inv * g[t]     + b[t]);
    out[base + t+256] = __float2half((x1 - mean) * inv * g[t+256] + b[t+256]);
    out[base + t+512] = __float2half((x2 - mean) * inv * g[t+512] + b[t+512]);
}

/* ---------------- fused pre-mix + softmax + post-mix -> fp16 padded ---------------- */
__global__ void __launch_bounds__(224)
k_mix_softmax(const float* __restrict__ a, const float* __restrict__ wpre,
              const float* __restrict__ wpost, __half* __restrict__ af) {
    int b = blockIdx.x / N_, n = blockIdx.x % N_;
    __shared__ float sm_[H_][208];
    __shared__ float ws1[H_*H_], ws2[H_*H_];
    int tid = threadIdx.x, wid = tid >> 5, lane = tid & 31;
    if (tid < H_*H_) { ws1[tid] = wpre[tid]; ws2[tid] = wpost[tid]; }
    __syncthreads();
    if (tid < N_) {
        float vals[H_];
        #pragma unroll
        for (int h = 0; h < H_; h++)
            vals[h] = a[((size_t)(b*H_ + h) * N_ + n) * N_ + tid];
        #pragma unroll
        for (int gg = 0; gg < H_; gg++) {
            float s = 0.f;
            #pragma unroll
            for (int h = 0; h < H_; h++) s += ws1[gg*H_ + h] * vals[h];
            sm_[gg][tid] = s;
        }
    }
    __syncthreads();
    for (int r = wid; r < H_; r += 7) {
        float v[7];
        float mx = -1e30f;
        #pragma unroll
        for (int i = 0; i < 7; i++) {
            int c = lane + i*32;
            v[i] = (c < N_) ? sm_[r][c] : -1e30f;
            mx = fmaxf(mx, v[i]);
        }
        for (int o = 16; o; o >>= 1) mx = fmaxf(mx, __shfl_xor_sync(0xffffffffu, mx, o));
        float s = 0.f;
        #pragma unroll
        for (int i = 0; i < 7; i++) {
            int c = lane + i*32;
            v[i] = (c < N_) ? __expf(v[i] - mx) : 0.f;
            s += v[i];
        }
        for (int o = 16; o; o >>= 1) s += __shfl_xor_sync(0xffffffffu, s, o);
        float inv = 1.f / s;
        #pragma unroll
        for (int i = 0; i < 7; i++) {
            int c = lane + i*32;
            if (c < N_) sm_[r][c] = v[i] * inv;
        }
    }
    __syncthreads();
    if (tid < N_) {
        float vals[H_];
        #pragma unroll
        for (int h = 0; h < H_; h++) vals[h] = sm_[h][tid];
        #pragma unroll
        for (int gg = 0; gg < H_; gg++) {
            float s = 0.f;
            #pragma unroll
            for (int h = 0; h < H_; h++) s += ws2[gg*H_ + h] * vals[h];
            af[((size_t)(b*H_ + gg) * N_ + n) * KPAD_ + tid] = __float2half(s);
        }
    } else {
        #pragma unroll
        for (int gg = 0; gg < H_; gg++)
            af[((size_t)(b*H_ + gg) * N_ + n) * KPAD_ + tid] = __float2half(0.f);
    }
}

/* ---------------- launch ---------------- */
static inline void* sym(const void* s) { void* p; cudaGetSymbolAddress(&p, s); return p; }

extern "C" void kernel_launch(void* const* d_in, const int* in_sizes, int n_in,
                              void* d_out, int out_size) {
    const float* x      = (const float*)d_in[0];
    const float* Wpe    = (const float*)d_in[1];
    const float* bpe    = (const float*)d_in[2];
    const float* cls    = (const float*)d_in[3];
    const float* pos    = (const float*)d_in[4];
    const float* ln1_g  = (const float*)d_in[5];
    const float* ln1_b  = (const float*)d_in[6];
    const float* qkv_w  = (const float*)d_in[7];
    const float* qkv_b  = (const float*)d_in[8];
    const float* pre_w  = (const float*)d_in[9];
    const float* post_w = (const float*)d_in[10];
    const float* proj_w = (const float*)d_in[11];
    const float* proj_b = (const float*)d_in[12];
    const float* ln2_g  = (const float*)d_in[13];
    const float* ln2_b  = (const float*)d_in[14];
    const float* fc1_w  = (const float*)d_in[15];
    const float* fc1_b  = (const float*)d_in[16];
    const float* fc2_w  = (const float*)d_in[17];
    const float* fc2_b  = (const float*)d_in[18];
    const float* lnf_g  = (const float*)d_in[19];
    const float* lnf_b  = (const float*)d_in[20];
    const float* head_w = (const float*)d_in[21];
    const float* head_b = (const float*)d_in[22];
    float* out = (float*)d_out;

    float* pe = (float*)sym(g_pe);
    float* t  = (float*)sym(g_t);
    float* a  = (float*)sym(g_a);
    float* sk = (float*)sym(g_sk);
    __half* wpeh = (__half*)sym(g_wpe);
    __half* wqkv = (__half*)sym(g_wqkv);
    __half* wprj = (__half*)sym(g_wprj);
    __half* wfc1 = (__half*)sym(g_wfc1);
    __half* wfc2 = (__half*)sym(g_wfc2);
    __half* whd  = (__half*)sym(g_whd);
    __half* xh = (__half*)sym(g_xh);
    __half* af = (__half*)sym(g_af);
    __half* oh = (__half*)sym(g_oh);
    __half* mh = (__half*)sym(g_mh);
    __half* vt = (__half*)sym(g_vt);

    cudaFuncSetAttribute(k_hgemm<0,128>, cudaFuncAttributeMaxDynamicSharedMemorySize, GSMEM);
    cudaFuncSetAttribute(k_hgemm<1,128>, cudaFuncAttributeMaxDynamicSharedMemorySize, GSMEM);
    cudaFuncSetAttribute(k_hgemm<2,128>, cudaFuncAttributeMaxDynamicSharedMemorySize, GSMEM);
    cudaFuncSetAttribute(k_hgemm<3,128>, cudaFuncAttributeMaxDynamicSharedMemorySize, GSMEM);
    cudaFuncSetAttribute(k_hgemm<5,64>,  cudaFuncAttributeMaxDynamicSharedMemorySize, GSMEM);
    cudaFuncSetAttribute(k_hgemm<6,128>, cudaFuncAttributeMaxDynamicSharedMemorySize, GSMEM);
    cudaFuncSetAttribute(k_hgemm<7,128>, cudaFuncAttributeMaxDynamicSharedMemorySize, GSMEM);

    /* early launches ordered so ncu's skip count lands on a representative GEMM */
    { int n4 = D_*768/4;          k_convert<<<(n4+255)/256, 256>>>(Wpe, wpeh, n4); }        /* 0 */
    k_patch_gather<<<(PTOK_*D_ + 255)/256, 256>>>(x, xh);                                   /* 1 */
    { int n4 = DEPTH_*QKVD_*D_/4; k_convert<<<(n4+255)/256, 256>>>(qkv_w, wqkv, n4); }      /* 2 */
    k_hgemm<0,128><<<dim3(6, 49, 1), 256, GSMEM>>>(xh, wpeh, bpe, nullptr, pe, nullptr,     /* 3 */
                                                   PTOK_, D_, D_, D_, D_, D_, 1, 0,0,0,0,0,0);
    k_assemble<<<(TOK_*D_ + 255)/256, 256>>>(pe, cls, pos, t);                              /* 4 */
    { int n4 = DEPTH_*D_*D_/4;    k_convert<<<(n4+255)/256, 256>>>(proj_w, wprj, n4); }     /* 5 */
    { int n4 = DEPTH_*MLP_*D_/4;  k_convert<<<(n4+255)/256, 256>>>(fc1_w, wfc1, n4); }
    { int n4 = DEPTH_*D_*MLP_/4;  k_convert<<<(n4+255)/256, 256>>>(fc2_w, wfc2, n4); }
    { int n4 = 1000*D_/4;         k_convert<<<(n4+255)/256, 256>>>(head_w, whd, n4); }
    { int nv = B_*H_*HD_*KPAD_;   k_zero_h<<<(nv+255)/256, 256>>>(vt, nv); }
    /* layer 0 LN1 (subsequent LN1s are fused into k_skred_ln) */
    k_layernorm<<<TOK_, 256>>>(t, ln1_g, ln1_b, xh, D_);

    for (int L = 0; L < DEPTH_; L++) {
        const __half* qw = wqkv + (size_t)L*QKVD_*D_;
        const float* qb  = qkv_b + L*QKVD_;
        const float* wpr = pre_w  + L*H_*H_;
        const float* wpo = post_w + L*H_*H_;
        const __half* pw = wprj + (size_t)L*D_*D_;
        const float* pb  = proj_b + L*D_;
        const float* l2g = ln2_g + L*D_;
        const float* l2b = ln2_b + L*D_;
        const __half* f1w = wfc1 + (size_t)L*MLP_*D_;
        const float* f1b = fc1_b + L*MLP_;
        const __half* f2w = wfc2 + (size_t)L*D_*MLP_;
        const float* f2b = fc2_b + L*D_;

        /* QKV + scatter to per-head Q, K, V^T (xh holds LN1 output) */
        k_hgemm<6,128><<<dim3(18, 50, 1), 256, GSMEM>>>(xh, qw, qb, nullptr, nullptr, nullptr,
                                                        TOK_, QKVD_, D_, D_, D_, 0, 1, 0,0,0,0,0,0);
        /* scores = Q K^T * scale  (batched over bh) */
        k_hgemm<3,128><<<dim3(2, 2, B_*H_), 256, GSMEM>>>(
            (const __half*)sym(g_qh), (const __half*)sym(g_kh), nullptr, nullptr,
            a, nullptr, N_, N_, HD_, HD_, HD_, N_,
            1, (long long)N_*HD_, 0, (long long)N_*HD_, 0, (long long)NN_, 0);
        k_mix_softmax<<<B_*N_, 224>>>(a, wpr, wpo, af);
        /* O = A V  (batched over bh, K padded to 224; NTILE=64 — no wasted half) */
        k_hgemm<5,64><<<dim3(1, 2, B_*H_), 256, GSMEM>>>(
            af, vt, nullptr, nullptr, nullptr, oh,
            N_, HD_, KPAD_, KPAD_, KPAD_, D_,
            H_, (long long)H_*N_*KPAD_, (long long)N_*KPAD_,
            (long long)H_*HD_*KPAD_, (long long)HD_*KPAD_,
            (long long)N_*D_, (long long)HD_);
        /* proj + residual */
        k_hgemm<2,128><<<dim3(6, 50, 1), 256, GSMEM>>>(oh, pw, pb, t, t, nullptr,
                                                       TOK_, D_, D_, D_, D_, D_, 1, 0,0,0,0,0,0);
        k_layernorm<<<TOK_, 256>>>(t, l2g, l2b, xh, D_);
        /* fc1 + GELU -> fp16 */
        k_hgemm<1,128><<<dim3(24, 50, 1), 256, GSMEM>>>(xh, f1w, f1b, nullptr, nullptr, mh,
                                                        TOK_, MLP_, D_, D_, D_, MLP_, 1, 0,0,0,0,0,0);
        /* fc2 split-K=4 partials */
        k_hgemm<7,128><<<dim3(6, 50, 4), 256, GSMEM>>>(mh, f2w, nullptr, nullptr, sk, nullptr,
                                                       TOK_, D_, MLP_/4, MLP_, MLP_, D_,
                                                       4, 0, MLP_/4, 0, MLP_/4, 0, (long long)TOK_*D_);
        if (L < DEPTH_ - 1) {
            /* fused: reduce + bias + residual -> t, then next layer's LN1 -> xh */
            k_skred_ln<<<TOK_, 256>>>(t, sk, f2b, ln1_g + (L+1)*D_, ln1_b + (L+1)*D_, xh);
        } else {
            k_skred<1><<<(TOK_*D_/4 + 255)/256, 256>>>(t, sk, f2b, TOK_*D_/4, D_,
                                                       (long long)TOK_*D_/4, 4);
        }
    }

    /* final LN on cls rows only, then head (split-K=8) */
    k_layernorm<<<B_, 256>>>(t, lnf_g, lnf_b, xh, (size_t)N_*D_);
    k_hgemm<7,128><<<dim3(8, 1, 8), 256, GSMEM>>>(xh, whd, nullptr, nullptr, sk, nullptr,
                                                  B_, 1000, D_/8, D_, D_, 1000,
                                                  8, 0, D_/8, 0, D_/8, 0, (long long)B_*1000);
    k_skred<0><<<(B_*1000/4 + 255)/256, 256>>>(out, sk, head_b, B_*1000/4, 1000,
                                               (long long)B_*1000/4, 8);
}